// round 3
// baseline (speedup 1.0000x reference)
#include <cuda_runtime.h>
#include <cuda_fp16.h>
#include <cuda_bf16.h>
#include <math.h>

// Problem constants
#define NN 4096
#define NF 512
#define NH 8
#define NC 64
#define HC 512           // NH*NC
#define TC 72            // X-tilde cols: 64 feat + 1 ones + 7 pad

// -------- scratch (device globals; no allocation allowed) --------
__device__ float  g_wl[NH * NF];            // W @ att_l per head (512-vec)
__device__ float  g_wr[NH * NF];
__device__ float  g_bl[NH], g_br[NH];
__device__ float  g_alT[NH * NN];           // alpha_l, [h][n]
__device__ float  g_arT[NH * NN];           // alpha_r, [h][n]
__device__ float  g_rmax[NH], g_rmin[NH];
__device__ __half g_X[(size_t)NH * NN * TC];// [h][j][72] fp16 (feat|1|pad0)

// =================================================================
// K0: per-head projected attention vectors  wl[h] = W_h @ att_l[h]
// =================================================================
__global__ void __launch_bounds__(256) k_prepw(const float* __restrict__ W,
                                               const float* __restrict__ b,
                                               const float* __restrict__ attl,
                                               const float* __restrict__ attr) {
    int idx = blockIdx.x * 256 + threadIdx.x;
    if (idx < 2 * NH * NF) {
        int side = idx >> 12;
        int h = (idx >> 9) & 7;
        int k = idx & 511;
        const float* av = (side ? attr : attl) + h * NC;
        const float* wr = W + (size_t)k * HC + h * NC;
        float s = 0.0f;
#pragma unroll
        for (int c = 0; c < NC; c++) s = fmaf(wr[c], av[c], s);
        (side ? g_wr : g_wl)[h * NF + k] = s;
    }
    if (idx < 16) {
        int side = idx >> 3, h = idx & 7;
        const float* av = (side ? attr : attl) + h * NC;
        float s = 0.0f;
#pragma unroll
        for (int c = 0; c < NC; c++) s = fmaf(b[h * NC + c], av[c], s);
        (side ? g_br : g_bl)[h] = s;
    }
}

// =================================================================
// K1: x_l = x @ W + b  (fp16 MMA, 4096x512x512), writes X-tilde directly
// =================================================================
__global__ void __launch_bounds__(256) k_xl16(const float* __restrict__ x,
                                              const float* __restrict__ W,
                                              const float* __restrict__ Bv) {
    __shared__ __align__(16) unsigned sAu[128 * 18];   // A halves as uint pairs
    __shared__ __align__(16) unsigned sBu[64 * 18];    // B^T halves as uint pairs
    __half* sBh = (__half*)sBu;                        // row stride 36 halfs

    int h = blockIdx.x;                 // one head (64 cols) per n-block
    int m0 = blockIdx.y * 128;
    int tid = threadIdx.x;
    int warp = tid >> 5, lane = tid & 31;
    int gid = lane >> 2, tig = lane & 3;
    int mw = warp & 3, nw = warp >> 2;  // 4 m-groups x 2 n-groups

    float acc[2][4][4];
#pragma unroll
    for (int mi = 0; mi < 2; mi++)
#pragma unroll
        for (int ni = 0; ni < 4; ni++)
#pragma unroll
            for (int q = 0; q < 4; q++) acc[mi][ni][q] = 0.0f;

    for (int k0 = 0; k0 < NF; k0 += 32) {
        // A: 128 rows x 32 k floats -> half2 uints
#pragma unroll
        for (int q = 0; q < 8; q++) {
            int u = q * 256 + tid;
            int r = u >> 4, cp = u & 15;
            float2 v = *(const float2*)(x + (size_t)(m0 + r) * NF + k0 + 2 * cp);
            __half2 hh = __floats2half2_rn(v.x, v.y);
            sAu[r * 18 + cp] = *(unsigned*)&hh;
        }
        // B: W rows k0..k0+31, cols h*64..+63, transposed into [n][k]
#pragma unroll
        for (int q = 0; q < 8; q++) {
            int idx = q * 256 + tid;
            int r = idx >> 6, c = idx & 63;
            float v = W[(size_t)(k0 + r) * HC + h * NC + c];
            sBh[c * 36 + r] = __float2half(v);
        }
        __syncthreads();
#pragma unroll
        for (int ki = 0; ki < 2; ki++) {
            unsigned af[2][4];
#pragma unroll
            for (int mi = 0; mi < 2; mi++) {
                int r0 = mw * 32 + mi * 16 + gid;
                af[mi][0] = sAu[(r0)     * 18 + ki * 8 + tig];
                af[mi][1] = sAu[(r0 + 8) * 18 + ki * 8 + tig];
                af[mi][2] = sAu[(r0)     * 18 + ki * 8 + tig + 4];
                af[mi][3] = sAu[(r0 + 8) * 18 + ki * 8 + tig + 4];
            }
#pragma unroll
            for (int ni = 0; ni < 4; ni++) {
                int n = nw * 32 + ni * 8 + gid;
                unsigned b0 = sBu[n * 18 + ki * 8 + tig];
                unsigned b1 = sBu[n * 18 + ki * 8 + tig + 4];
#pragma unroll
                for (int mi = 0; mi < 2; mi++) {
                    asm volatile(
                        "mma.sync.aligned.m16n8k16.row.col.f32.f16.f16.f32 "
                        "{%0,%1,%2,%3}, {%4,%5,%6,%7}, {%8,%9}, {%0,%1,%2,%3};\n"
                        : "+f"(acc[mi][ni][0]), "+f"(acc[mi][ni][1]),
                          "+f"(acc[mi][ni][2]), "+f"(acc[mi][ni][3])
                        : "r"(af[mi][0]), "r"(af[mi][1]),
                          "r"(af[mi][2]), "r"(af[mi][3]),
                          "r"(b0), "r"(b1));
                }
            }
        }
        __syncthreads();
    }
    // epilogue: + bias, write fp16 into g_X[h][row][c]
    __half* Xh = g_X + (size_t)h * NN * TC;
#pragma unroll
    for (int mi = 0; mi < 2; mi++)
#pragma unroll
        for (int ni = 0; ni < 4; ni++) {
            int r0 = m0 + mw * 32 + mi * 16 + gid;
            int cc = nw * 32 + ni * 8 + tig * 2;
            float b0 = Bv[h * NC + cc], b1 = Bv[h * NC + cc + 1];
            __half2 v0 = __floats2half2_rn(acc[mi][ni][0] + b0, acc[mi][ni][1] + b1);
            __half2 v1 = __floats2half2_rn(acc[mi][ni][2] + b0, acc[mi][ni][3] + b1);
            *(unsigned*)&Xh[(size_t)r0 * TC + cc]       = *(unsigned*)&v0;
            *(unsigned*)&Xh[(size_t)(r0 + 8) * TC + cc] = *(unsigned*)&v1;
        }
    if (tid < 128) {   // ones column + zero pad
        unsigned* xr = (unsigned*)(g_X + (size_t)h * NN * TC + (size_t)(m0 + tid) * TC);
        xr[32] = 0x00003C00u;  // {1.0h, 0h}
        xr[33] = 0u; xr[34] = 0u; xr[35] = 0u;
    }
}

// =================================================================
// K2: exact fp32 alphas: alpha[n,h] = x[n,:] @ w[h,:] + bhat[h]
// =================================================================
__global__ void __launch_bounds__(256) k_alpha2(const float* __restrict__ x) {
    __shared__ float sx[NF];
    int n = blockIdx.x;
    int tid = threadIdx.x;
    sx[tid]       = x[(size_t)n * NF + tid];
    sx[tid + 256] = x[(size_t)n * NF + tid + 256];
    __syncthreads();
    int w = tid >> 5, lane = tid & 31;
    float sl = 0.0f, sr = 0.0f;
#pragma unroll
    for (int i = 0; i < 16; i++) {
        float xv = sx[lane + 32 * i];
        sl = fmaf(xv, g_wl[w * NF + lane + 32 * i], sl);
        sr = fmaf(xv, g_wr[w * NF + lane + 32 * i], sr);
    }
#pragma unroll
    for (int o = 16; o; o >>= 1) {
        sl += __shfl_xor_sync(0xFFFFFFFFu, sl, o);
        sr += __shfl_xor_sync(0xFFFFFFFFu, sr, o);
    }
    if (lane == 0) {
        g_alT[w * NN + n] = sl + g_bl[w];
        g_arT[w * NN + n] = sr + g_br[w];
    }
}

// =================================================================
// K3: per-head global max/min of alpha_r (single block, 512 thr)
// =================================================================
__global__ void __launch_bounds__(512) k_rstat() {
    int tid = threadIdx.x;
    int h = tid >> 6, j0 = tid & 63;
    float mx = -3.0e38f, mn = 3.0e38f;
    for (int j = j0; j < NN; j += 64) {
        float v = g_arT[h * NN + j];
        mx = fmaxf(mx, v);
        mn = fminf(mn, v);
    }
    __shared__ float smx[512], smn[512];
    smx[tid] = mx; smn[tid] = mn;
    __syncthreads();
    for (int s = 32; s >= 1; s >>= 1) {
        if ((tid & 63) < s) {
            smx[tid] = fmaxf(smx[tid], smx[tid + s]);
            smn[tid] = fminf(smn[tid], smn[tid + s]);
        }
        __syncthreads();
    }
    if ((tid & 63) == 0) { g_rmax[h] = smx[tid]; g_rmin[h] = smn[tid]; }
}

// =================================================================
// K4 (fused): per head, C[128x72] tiles of P_h @ X_h with P computed
// in-smem from adj + alphas. Epilogue: out = relu(C[:, :64] / C[:, 64]).
// =================================================================
#define MT 128
#define KT 64
__global__ void __launch_bounds__(128) k_aggF(const int* __restrict__ adj,
                                              float* __restrict__ out) {
    // layout: sA [0,18432) | sB [18432,28800) | sAL [28800,29312) | sM [29312,29824)
    // epilogue Cs overlays [0, 37376)
    __shared__ __align__(16) unsigned char smem_raw[38400];
    unsigned* sA  = (unsigned*)smem_raw;                   // [128][36] uint pairs
    unsigned* sBu = (unsigned*)(smem_raw + 18432);         // [72][36]
    __half*   sBh = (__half*)sBu;
    float*    sAL = (float*)(smem_raw + 28800);            // alpha_l per row
    float*    sM  = (float*)(smem_raw + 29312);            // row max bound
    float*    Cs  = (float*)smem_raw;                      // [128][73]

    int h = blockIdx.y;
    int i0 = blockIdx.x * MT;
    int tid = threadIdx.x;
    int warp = tid >> 5, lane = tid & 31;
    int gid = lane >> 2, tig = lane & 3;

    float rmx = g_rmax[h], rmn = g_rmin[h];
    {
        float al = g_alT[h * NN + i0 + tid];
        sAL[tid] = al;
        sM[tid] = (al >= 0.0f) ? al * rmx : al * rmn;
    }
    const __half* Bh = g_X + (size_t)h * NN * TC;

    float acc[2][9][4];
#pragma unroll
    for (int mi = 0; mi < 2; mi++)
#pragma unroll
        for (int ni = 0; ni < 9; ni++)
#pragma unroll
            for (int q = 0; q < 4; q++) acc[mi][ni][q] = 0.0f;
    __syncthreads();

    for (int k0 = 0; k0 < NN; k0 += KT) {
        // ---- build P tile in sA: 128 rows x 64 cols fp16 ----
        const int2*   adj2 = (const int2*)(adj + (size_t)i0 * NN + k0);
        const float2* ar2  = (const float2*)(g_arT + h * NN + k0);
#pragma unroll
        for (int q = 0; q < 32; q++) {
            int u = q * 128 + tid;
            int r = u >> 5, cp = u & 31;
            int2 e = adj2[(size_t)r * (NN / 2) + cp];
            float2 rr = ar2[cp];
            float al = sAL[r], mm = sM[r];
            float w0 = (e.x > 0) ? __expf(fmaf(al, rr.x, -mm)) : 0.0f;
            float w1 = (e.y > 0) ? __expf(fmaf(al, rr.y, -mm)) : 0.0f;
            __half2 hh = __floats2half2_rn(w0, w1);
            sA[r * 36 + cp] = *(unsigned*)&hh;
        }
        // ---- load B tile 64x72 halfs, transpose into sBh[n][k] ----
        const unsigned* gB = (const unsigned*)(Bh + (size_t)k0 * TC);
#pragma unroll
        for (int q = 0; q < 18; q++) {
            int idx = q * 128 + tid;            // 0..2303
            int r = idx / 36, c = idx - r * 36; // j-row, half-pair
            unsigned v = gB[r * 36 + c];
            sBh[(2 * c) * TC + r]     = __ushort_as_half((unsigned short)(v & 0xFFFF));
            sBh[(2 * c + 1) * TC + r] = __ushort_as_half((unsigned short)(v >> 16));
        }
        __syncthreads();

        int mbase = warp * 32;
#pragma unroll
        for (int ki = 0; ki < 4; ki++) {
            unsigned afr[2][4];
#pragma unroll
            for (int mi = 0; mi < 2; mi++) {
                int r0 = mbase + mi * 16 + gid;
                afr[mi][0] = sA[(r0)     * 36 + ki * 8 + tig];
                afr[mi][1] = sA[(r0 + 8) * 36 + ki * 8 + tig];
                afr[mi][2] = sA[(r0)     * 36 + ki * 8 + tig + 4];
                afr[mi][3] = sA[(r0 + 8) * 36 + ki * 8 + tig + 4];
            }
#pragma unroll
            for (int ni = 0; ni < 9; ni++) {
                int n = ni * 8 + gid;
                unsigned b0 = sBu[n * 36 + ki * 8 + tig];
                unsigned b1 = sBu[n * 36 + ki * 8 + tig + 4];
#pragma unroll
                for (int mi = 0; mi < 2; mi++) {
                    asm volatile(
                        "mma.sync.aligned.m16n8k16.row.col.f32.f16.f16.f32 "
                        "{%0,%1,%2,%3}, {%4,%5,%6,%7}, {%8,%9}, {%0,%1,%2,%3};\n"
                        : "+f"(acc[mi][ni][0]), "+f"(acc[mi][ni][1]),
                          "+f"(acc[mi][ni][2]), "+f"(acc[mi][ni][3])
                        : "r"(afr[mi][0]), "r"(afr[mi][1]),
                          "r"(afr[mi][2]), "r"(afr[mi][3]),
                          "r"(b0), "r"(b1));
                }
            }
        }
        __syncthreads();
    }

    // ---- epilogue: normalize by ones-column, relu, store ----
#pragma unroll
    for (int mi = 0; mi < 2; mi++)
#pragma unroll
        for (int ni = 0; ni < 9; ni++) {
            int r0 = warp * 32 + mi * 16 + gid;
            int cc = ni * 8 + tig * 2;
            Cs[(r0)     * 73 + cc]     = acc[mi][ni][0];
            Cs[(r0)     * 73 + cc + 1] = acc[mi][ni][1];
            Cs[(r0 + 8) * 73 + cc]     = acc[mi][ni][2];
            Cs[(r0 + 8) * 73 + cc + 1] = acc[mi][ni][3];
        }
    __syncthreads();
#pragma unroll
    for (int q = 0; q < 64; q++) {
        int idx = q * 128 + tid;
        int r = idx >> 6, c = idx & 63;
        float z = Cs[r * 73 + 64];
        float v = Cs[r * 73 + c];
        v = (z > 0.0f) ? (v / z) : 0.0f;
        out[(size_t)(i0 + r) * HC + h * NC + c] = fmaxf(v, 0.0f);
    }
}

// =================================================================
extern "C" void kernel_launch(void* const* d_in, const int* in_sizes, int n_in,
                              void* d_out, int out_size) {
    const float* x     = (const float*)d_in[0];
    const int*   adj   = (const int*)d_in[1];
    const float* W     = (const float*)d_in[2];
    const float* b     = (const float*)d_in[3];
    const float* att_l = (const float*)d_in[4];
    const float* att_r = (const float*)d_in[5];
    float* out = (float*)d_out;

    k_prepw<<<32, 256>>>(W, b, att_l, att_r);
    k_xl16<<<dim3(NH, NN / 128), 256>>>(x, W, b);
    k_alpha2<<<NN, 256>>>(x);
    k_rstat<<<1, 512>>>();
    k_aggF<<<dim3(NN / MT, NH), 128>>>(adj, out);
}

// round 5
// speedup vs baseline: 1.5099x; 1.5099x over previous
#include <cuda_runtime.h>
#include <cuda_fp16.h>
#include <cuda_bf16.h>
#include <math.h>

// Problem constants
#define NN 4096
#define NF 512
#define NH 8
#define NC 64
#define HC 512           // NH*NC
#define TC 72            // X-tilde cols: 64 feat + 1 ones + 7 pad

// -------- scratch (device globals; no allocation allowed) --------
__device__ float    g_wl[NH * NF];            // W @ att_l per head (512-vec)
__device__ float    g_wr[NH * NF];
__device__ float    g_bl[NH], g_br[NH];
__device__ float    g_alT[NH * NN];           // alpha_l, [h][n]
__device__ float    g_arT[NH * NN];           // alpha_r, [h][n]
__device__ float    g_rmax[NH], g_rmin[NH];
__device__ __half   g_X[(size_t)NH * NN * TC];// [h][j][72] fp16 (feat|1|pad0)
__device__ unsigned g_adjbits[(size_t)NN * 128]; // adj packed to bits, 2MB

// =================================================================
// K-1: pack adj into bitmask. One block per row, ballot per warp.
// =================================================================
__global__ void __launch_bounds__(256) k_pack(const int* __restrict__ adj) {
    int i = blockIdx.x;
    int warp = threadIdx.x >> 5, lane = threadIdx.x & 31;
    const int* row = adj + (size_t)i * NN;
#pragma unroll
    for (int w = warp; w < 128; w += 8) {
        int v = __ldg(&row[w * 32 + lane]);
        unsigned m = __ballot_sync(0xFFFFFFFFu, v > 0);
        if (lane == 0) g_adjbits[i * 128 + w] = m;
    }
}

// =================================================================
// K0: per-head projected attention vectors  wl[h] = W_h @ att_l[h]
// =================================================================
__global__ void __launch_bounds__(256) k_prepw(const float* __restrict__ W,
                                               const float* __restrict__ b,
                                               const float* __restrict__ attl,
                                               const float* __restrict__ attr) {
    int idx = blockIdx.x * 256 + threadIdx.x;
    if (idx < 2 * NH * NF) {
        int side = idx >> 12;
        int h = (idx >> 9) & 7;
        int k = idx & 511;
        const float* av = (side ? attr : attl) + h * NC;
        const float* wr = W + (size_t)k * HC + h * NC;
        float s = 0.0f;
#pragma unroll
        for (int c = 0; c < NC; c++) s = fmaf(wr[c], av[c], s);
        (side ? g_wr : g_wl)[h * NF + k] = s;
    }
    if (idx < 16) {
        int side = idx >> 3, h = idx & 7;
        const float* av = (side ? attr : attl) + h * NC;
        float s = 0.0f;
#pragma unroll
        for (int c = 0; c < NC; c++) s = fmaf(b[h * NC + c], av[c], s);
        (side ? g_br : g_bl)[h] = s;
    }
}

// =================================================================
// K1: x_l = x @ W + b  (fp16 MMA), writes X-tilde directly
// =================================================================
__global__ void __launch_bounds__(256) k_xl16(const float* __restrict__ x,
                                              const float* __restrict__ W,
                                              const float* __restrict__ Bv) {
    __shared__ __align__(16) unsigned sAu[128 * 18];   // A halves as uint pairs
    __shared__ __align__(16) unsigned sBu[64 * 18];    // B^T halves as uint pairs
    __half* sBh = (__half*)sBu;                        // row stride 36 halfs

    int h = blockIdx.x;                 // one head (64 cols) per n-block
    int m0 = blockIdx.y * 128;
    int tid = threadIdx.x;
    int warp = tid >> 5, lane = tid & 31;
    int gid = lane >> 2, tig = lane & 3;
    int mw = warp & 3, nw = warp >> 2;  // 4 m-groups x 2 n-groups

    float acc[2][4][4];
#pragma unroll
    for (int mi = 0; mi < 2; mi++)
#pragma unroll
        for (int ni = 0; ni < 4; ni++)
#pragma unroll
            for (int q = 0; q < 4; q++) acc[mi][ni][q] = 0.0f;

    for (int k0 = 0; k0 < NF; k0 += 32) {
#pragma unroll
        for (int q = 0; q < 8; q++) {
            int u = q * 256 + tid;
            int r = u >> 4, cp = u & 15;
            float2 v = *(const float2*)(x + (size_t)(m0 + r) * NF + k0 + 2 * cp);
            __half2 hh = __floats2half2_rn(v.x, v.y);
            sAu[r * 18 + cp] = *(unsigned*)&hh;
        }
#pragma unroll
        for (int q = 0; q < 8; q++) {
            int idx = q * 256 + tid;
            int r = idx >> 6, c = idx & 63;
            float v = W[(size_t)(k0 + r) * HC + h * NC + c];
            sBh[c * 36 + r] = __float2half(v);
        }
        __syncthreads();
#pragma unroll
        for (int ki = 0; ki < 2; ki++) {
            unsigned af[2][4];
#pragma unroll
            for (int mi = 0; mi < 2; mi++) {
                int r0 = mw * 32 + mi * 16 + gid;
                af[mi][0] = sAu[(r0)     * 18 + ki * 8 + tig];
                af[mi][1] = sAu[(r0 + 8) * 18 + ki * 8 + tig];
                af[mi][2] = sAu[(r0)     * 18 + ki * 8 + tig + 4];
                af[mi][3] = sAu[(r0 + 8) * 18 + ki * 8 + tig + 4];
            }
#pragma unroll
            for (int ni = 0; ni < 4; ni++) {
                int n = nw * 32 + ni * 8 + gid;
                unsigned b0 = sBu[n * 18 + ki * 8 + tig];
                unsigned b1 = sBu[n * 18 + ki * 8 + tig + 4];
#pragma unroll
                for (int mi = 0; mi < 2; mi++) {
                    asm volatile(
                        "mma.sync.aligned.m16n8k16.row.col.f32.f16.f16.f32 "
                        "{%0,%1,%2,%3}, {%4,%5,%6,%7}, {%8,%9}, {%0,%1,%2,%3};\n"
                        : "+f"(acc[mi][ni][0]), "+f"(acc[mi][ni][1]),
                          "+f"(acc[mi][ni][2]), "+f"(acc[mi][ni][3])
                        : "r"(af[mi][0]), "r"(af[mi][1]),
                          "r"(af[mi][2]), "r"(af[mi][3]),
                          "r"(b0), "r"(b1));
                }
            }
        }
        __syncthreads();
    }
    __half* Xh = g_X + (size_t)h * NN * TC;
#pragma unroll
    for (int mi = 0; mi < 2; mi++)
#pragma unroll
        for (int ni = 0; ni < 4; ni++) {
            int r0 = m0 + mw * 32 + mi * 16 + gid;
            int cc = nw * 32 + ni * 8 + tig * 2;
            float b0 = Bv[h * NC + cc], b1 = Bv[h * NC + cc + 1];
            __half2 v0 = __floats2half2_rn(acc[mi][ni][0] + b0, acc[mi][ni][1] + b1);
            __half2 v1 = __floats2half2_rn(acc[mi][ni][2] + b0, acc[mi][ni][3] + b1);
            *(unsigned*)&Xh[(size_t)r0 * TC + cc]       = *(unsigned*)&v0;
            *(unsigned*)&Xh[(size_t)(r0 + 8) * TC + cc] = *(unsigned*)&v1;
        }
    if (tid < 128) {   // ones column + zero pad
        unsigned* xr = (unsigned*)(g_X + (size_t)h * NN * TC + (size_t)(m0 + tid) * TC);
        xr[32] = 0x00003C00u;  // {1.0h, 0h}
        xr[33] = 0u; xr[34] = 0u; xr[35] = 0u;
    }
}

// =================================================================
// K2: exact fp32 alphas: alpha[n,h] = x[n,:] @ w[h,:] + bhat[h]
// =================================================================
__global__ void __launch_bounds__(256) k_alpha2(const float* __restrict__ x) {
    __shared__ float sx[NF];
    int n = blockIdx.x;
    int tid = threadIdx.x;
    sx[tid]       = x[(size_t)n * NF + tid];
    sx[tid + 256] = x[(size_t)n * NF + tid + 256];
    __syncthreads();
    int w = tid >> 5, lane = tid & 31;
    float sl = 0.0f, sr = 0.0f;
#pragma unroll
    for (int i = 0; i < 16; i++) {
        float xv = sx[lane + 32 * i];
        sl = fmaf(xv, g_wl[w * NF + lane + 32 * i], sl);
        sr = fmaf(xv, g_wr[w * NF + lane + 32 * i], sr);
    }
#pragma unroll
    for (int o = 16; o; o >>= 1) {
        sl += __shfl_xor_sync(0xFFFFFFFFu, sl, o);
        sr += __shfl_xor_sync(0xFFFFFFFFu, sr, o);
    }
    if (lane == 0) {
        g_alT[w * NN + n] = sl + g_bl[w];
        g_arT[w * NN + n] = sr + g_br[w];
    }
}

// =================================================================
// K3: per-head global max/min of alpha_r. One block per head.
// =================================================================
__global__ void __launch_bounds__(256) k_rstat() {
    int h = blockIdx.x;
    int tid = threadIdx.x;
    float mx = -3.0e38f, mn = 3.0e38f;
    for (int j = tid; j < NN; j += 256) {
        float v = g_arT[h * NN + j];
        mx = fmaxf(mx, v);
        mn = fminf(mn, v);
    }
    __shared__ float smx[256], smn[256];
    smx[tid] = mx; smn[tid] = mn;
    __syncthreads();
    for (int s = 128; s >= 1; s >>= 1) {
        if (tid < s) {
            smx[tid] = fmaxf(smx[tid], smx[tid + s]);
            smn[tid] = fminf(smn[tid], smn[tid + s]);
        }
        __syncthreads();
    }
    if (tid == 0) { g_rmax[h] = smx[0]; g_rmin[h] = smn[0]; }
}

// =================================================================
// K4 (fused): per head, 64-row tiles of P_h @ X_h, P built in-smem
// from adj BITMASK + alphas. Epilogue: out = relu(C[:,:64]/C[:,64]).
// grid (64, 8), 256 threads (4 m-warps x 2 n-warps).
// =================================================================
#define MT 64
#define KT 64
__global__ void __launch_bounds__(256) k_aggF(float* __restrict__ out) {
    // sA [0, 9216) uint[64][36] | sB [9216, 19584) uint[72][36]
    // epilogue Cs overlays [0, 18688) float[64][73]
    __shared__ __align__(16) unsigned char smem_raw[19584];
    unsigned* sA  = (unsigned*)smem_raw;
    unsigned* sBu = (unsigned*)(smem_raw + 9216);
    __half*   sBh = (__half*)sBu;
    float*    Cs  = (float*)smem_raw;

    int h = blockIdx.y;
    int i0 = blockIdx.x * MT;
    int tid = threadIdx.x;
    int warp = tid >> 5, lane = tid & 31;
    int gid = lane >> 2, tig = lane & 3;
    int mw = warp & 3, nw = warp >> 2;

    // A-fill role: thread -> (row, 16-col quad)
    int arow = tid >> 2;
    int q4 = tid & 3;
    float al, mm;
    {
        float rmx = g_rmax[h], rmn = g_rmin[h];
        al = g_alT[h * NN + i0 + arow];
        mm = (al >= 0.0f) ? al * rmx : al * rmn;
    }
    const unsigned* bits = g_adjbits + (size_t)(i0 + arow) * 128 + (q4 >> 1);
    int shbase = (q4 & 1) * 16;
    const float* arp_base = g_arT + h * NN + q4 * 16;
    const __half* Bh = g_X + (size_t)h * NN * TC;

    float acc[5][4];
#pragma unroll
    for (int ni = 0; ni < 5; ni++)
#pragma unroll
        for (int q = 0; q < 4; q++) acc[ni][q] = 0.0f;

    for (int k0 = 0; k0 < NN; k0 += KT) {
        // ---- build P tile rows: 16 cols per thread from one bit-field ----
        {
            unsigned f = (bits[k0 >> 5] >> shbase) & 0xFFFFu;
            const float4* arp = (const float4*)(arp_base + k0);
            float va[16];
            *(float4*)&va[0]  = arp[0];
            *(float4*)&va[4]  = arp[1];
            *(float4*)&va[8]  = arp[2];
            *(float4*)&va[12] = arp[3];
#pragma unroll
            for (int p = 0; p < 8; p++) {
                float w0 = (f >> (2 * p))     & 1 ? __expf(fmaf(al, va[2 * p],     -mm)) : 0.0f;
                float w1 = (f >> (2 * p + 1)) & 1 ? __expf(fmaf(al, va[2 * p + 1], -mm)) : 0.0f;
                __half2 hh = __floats2half2_rn(w0, w1);
                sA[arow * 36 + q4 * 8 + p] = *(unsigned*)&hh;
            }
        }
        // ---- load B tile 64x72 halfs, transpose into sBh[n][k] ----
        const unsigned* gB = (const unsigned*)(Bh + (size_t)k0 * TC);
#pragma unroll
        for (int q = 0; q < 9; q++) {
            int idx = q * 256 + tid;            // 0..2303
            int r = idx / 36, c = idx - r * 36;
            unsigned v = gB[r * 36 + c];
            sBh[(2 * c) * TC + r]     = __ushort_as_half((unsigned short)(v & 0xFFFF));
            sBh[(2 * c + 1) * TC + r] = __ushort_as_half((unsigned short)(v >> 16));
        }
        __syncthreads();

#pragma unroll
        for (int ki = 0; ki < 4; ki++) {
            unsigned afr[4];
            int r0 = mw * 16 + gid;
            afr[0] = sA[(r0)     * 36 + ki * 8 + tig];
            afr[1] = sA[(r0 + 8) * 36 + ki * 8 + tig];
            afr[2] = sA[(r0)     * 36 + ki * 8 + tig + 4];
            afr[3] = sA[(r0 + 8) * 36 + ki * 8 + tig + 4];
#pragma unroll
            for (int ni = 0; ni < 5; ni++) {
                if (!(nw == 1 && ni == 4)) {
                    int n = nw * 40 + ni * 8 + gid;
                    unsigned b0 = sBu[n * 36 + ki * 8 + tig];
                    unsigned b1 = sBu[n * 36 + ki * 8 + tig + 4];
                    asm volatile(
                        "mma.sync.aligned.m16n8k16.row.col.f32.f16.f16.f32 "
                        "{%0,%1,%2,%3}, {%4,%5,%6,%7}, {%8,%9}, {%0,%1,%2,%3};\n"
                        : "+f"(acc[ni][0]), "+f"(acc[ni][1]),
                          "+f"(acc[ni][2]), "+f"(acc[ni][3])
                        : "r"(afr[0]), "r"(afr[1]), "r"(afr[2]), "r"(afr[3]),
                          "r"(b0), "r"(b1));
                }
            }
        }
        __syncthreads();
    }

    // ---- epilogue: dump, normalize by ones-column, relu, store ----
#pragma unroll
    for (int ni = 0; ni < 5; ni++) {
        if (!(nw == 1 && ni == 4)) {
            int r0 = mw * 16 + gid;
            int cc = nw * 40 + ni * 8 + tig * 2;
            Cs[(r0)     * 73 + cc]     = acc[ni][0];
            Cs[(r0)     * 73 + cc + 1] = acc[ni][1];
            Cs[(r0 + 8) * 73 + cc]     = acc[ni][2];
            Cs[(r0 + 8) * 73 + cc + 1] = acc[ni][3];
        }
    }
    __syncthreads();
#pragma unroll
    for (int q = 0; q < 16; q++) {
        int idx = q * 256 + tid;
        int r = idx >> 6, c = idx & 63;
        float z = Cs[r * 73 + 64];
        float v = Cs[r * 73 + c];
        v = (z > 0.0f) ? (v / z) : 0.0f;
        out[(size_t)(i0 + r) * HC + h * NC + c] = fmaxf(v, 0.0f);
    }
}

// =================================================================
extern "C" void kernel_launch(void* const* d_in, const int* in_sizes, int n_in,
                              void* d_out, int out_size) {
    const float* x     = (const float*)d_in[0];
    const int*   adj   = (const int*)d_in[1];
    const float* W     = (const float*)d_in[2];
    const float* b     = (const float*)d_in[3];
    const float* att_l = (const float*)d_in[4];
    const float* att_r = (const float*)d_in[5];
    float* out = (float*)d_out;

    k_pack<<<NN, 256>>>(adj);
    k_prepw<<<32, 256>>>(W, b, att_l, att_r);
    k_xl16<<<dim3(NH, NN / 128), 256>>>(x, W, b);
    k_alpha2<<<NN, 256>>>(x);
    k_rstat<<<NH, 256>>>();
    k_aggF<<<dim3(NN / MT, NH), 256>>>(out);
}

// round 6
// speedup vs baseline: 1.5819x; 1.0477x over previous
#include <cuda_runtime.h>
#include <cuda_fp16.h>
#include <cuda_bf16.h>
#include <math.h>

#define NN 4096
#define NF 512
#define NH 8
#define NC 64
#define HC 512
#define TC 72

// -------- scratch --------
__device__ float    g_wl[NH * NF], g_wr[NH * NF];
__device__ float    g_bl[NH], g_br[NH];
__device__ float    g_blb[HC];                      // bias copy for xl16 epilogue
__device__ float    g_alT[NH * NN];                 // alpha_l [h][n]
__device__ float    g_arT[NH * NN];                 // alpha_r [h][n]
__device__ unsigned g_rmaxu[NH], g_rminu[NH];       // monotone-coded stats
__device__ __half   g_XT[(size_t)NH * TC * NN];     // X-tilde TRANSPOSED [h][c][j]
__device__ unsigned g_adjbits[(size_t)NN * 128];    // adj bitmask, 2MB
__device__ __half   g_P[(size_t)NH * NN * NN];      // [h][i][j] fp16, 268MB

__device__ __forceinline__ unsigned fmono(float f) {
    unsigned u = __float_as_uint(f);
    return (u & 0x80000000u) ? ~u : (u | 0x80000000u);
}
__device__ __forceinline__ float fdec(unsigned u) {
    return __uint_as_float((u & 0x80000000u) ? (u ^ 0x80000000u) : ~u);
}

// =================================================================
// K1: pack adj | prepw | XT tail rows | stat init | bias copy
// =================================================================
__global__ void __launch_bounds__(256) k_prep(const int* __restrict__ adj,
                                              const float* __restrict__ W,
                                              const float* __restrict__ b,
                                              const float* __restrict__ attl,
                                              const float* __restrict__ attr) {
    int bb = blockIdx.x, tid = threadIdx.x;
    if (bb < 4096) {                    // ---- pack one adj row ----
        int warp = tid >> 5, lane = tid & 31;
        const int* row = adj + (size_t)bb * NN;
#pragma unroll
        for (int w = warp; w < 128; w += 8) {
            int v = __ldg(&row[w * 32 + lane]);
            unsigned m = __ballot_sync(0xFFFFFFFFu, v > 0);
            if (lane == 0) g_adjbits[bb * 128 + w] = m;
        }
    } else if (bb < 4128) {             // ---- prepw ----
        int idx = (bb - 4096) * 256 + tid;      // 0..8191
        int side = idx >> 12;
        int h = (idx >> 9) & 7;
        int k = idx & 511;
        const float* av = (side ? attr : attl) + h * NC;
        const float* wr = W + (size_t)k * HC + h * NC;
        float s = 0.0f;
#pragma unroll
        for (int c = 0; c < NC; c++) s = fmaf(wr[c], av[c], s);
        (side ? g_wr : g_wl)[h * NF + k] = s;
        if (idx < 16) {
            int sd = idx >> 3, hh = idx & 7;
            const float* av2 = (sd ? attr : attl) + hh * NC;
            float s2 = 0.0f;
#pragma unroll
            for (int c = 0; c < NC; c++) s2 = fmaf(b[hh * NC + c], av2[c], s2);
            (sd ? g_br : g_bl)[hh] = s2;
        }
        if (bb == 4096 && tid < 256) {  // bias copy (512 floats)
            g_blb[tid] = b[tid];
            g_blb[tid + 256] = b[tid + 256];
        }
    } else if (bb < 4640) {             // ---- XT tail rows: c=64 ones, 65..71 zero ----
        int idx = (bb - 4128) * 256 + tid;      // 0..131071 uints
        int h = idx >> 14;
        int rem = idx & 16383;
        int c = 64 + (rem >> 11);
        int ju = rem & 2047;
        ((unsigned*)g_XT)[((size_t)h * TC + c) * (NN / 2) + ju] =
            (c == 64) ? 0x3C003C00u : 0u;
    } else {                            // ---- stat init ----
        if (tid < NH) { g_rmaxu[tid] = 0u; g_rminu[tid] = 0xFFFFFFFFu; }
    }
}

// =================================================================
// K2: exact fp32 alphas + atomic per-head max/min of alpha_r
// =================================================================
__global__ void __launch_bounds__(256) k_alpha(const float* __restrict__ x) {
    __shared__ float sx[NF];
    int n = blockIdx.x;
    int tid = threadIdx.x;
    sx[tid]       = x[(size_t)n * NF + tid];
    sx[tid + 256] = x[(size_t)n * NF + tid + 256];
    __syncthreads();
    int w = tid >> 5, lane = tid & 31;
    float sl = 0.0f, sr = 0.0f;
#pragma unroll
    for (int i = 0; i < 16; i++) {
        float xv = sx[lane + 32 * i];
        sl = fmaf(xv, g_wl[w * NF + lane + 32 * i], sl);
        sr = fmaf(xv, g_wr[w * NF + lane + 32 * i], sr);
    }
#pragma unroll
    for (int o = 16; o; o >>= 1) {
        sl += __shfl_xor_sync(0xFFFFFFFFu, sl, o);
        sr += __shfl_xor_sync(0xFFFFFFFFu, sr, o);
    }
    if (lane == 0) {
        float vr = sr + g_br[w];
        g_alT[w * NN + n] = sl + g_bl[w];
        g_arT[w * NN + n] = vr;
        unsigned um = fmono(vr);
        atomicMax(&g_rmaxu[w], um);
        atomicMin(&g_rminu[w], um);
    }
}

// =================================================================
// K3 (union): blocks [0,8192) = pmat ; [8192,8448) = xl16 -> XT
// =================================================================
__global__ void __launch_bounds__(256) k_mid(const float* __restrict__ x,
                                             const float* __restrict__ W) {
    __shared__ __align__(16) unsigned char smem_raw[13888];
    int tid = threadIdx.x;

    if (blockIdx.x < 8192) {
        // ================= pmat: P[h][i][j] ======================
        int bq = blockIdx.x;
        int ib = bq & 511, jh = (bq >> 9) & 1, h = bq >> 10;
        float* s_ar = (float*)smem_raw;                 // 2048 floats
        float* s_al = (float*)(smem_raw + 8192);        // 8
        float* s_mm = s_al + 8;                         // 8
        {
            const float4* src = (const float4*)(g_arT + h * NN + jh * 2048);
            ((float4*)s_ar)[tid]       = src[tid];
            ((float4*)s_ar)[tid + 256] = src[tid + 256];
        }
        if (tid < 8) {
            float al = g_alT[h * NN + ib * 8 + tid];
            s_al[tid] = al;
            float rmx = fdec(g_rmaxu[h]), rmn = fdec(g_rminu[h]);
            s_mm[tid] = (al >= 0.0f) ? al * rmx : al * rmn;
        }
        __syncthreads();
        int j0 = jh * 2048 + tid * 8;
        float va[8];
        *(float4*)&va[0] = *(float4*)(s_ar + tid * 8);
        *(float4*)&va[4] = *(float4*)(s_ar + tid * 8 + 4);
        int sh = j0 & 24;
#pragma unroll
        for (int r = 0; r < 8; r++) {
            int i = ib * 8 + r;
            unsigned wb = g_adjbits[i * 128 + (j0 >> 5)];
            unsigned f = (wb >> sh) & 0xFFu;
            float al = s_al[r], mm = s_mm[r];
            __half2 h0 = __floats2half2_rn(
                (f & 1u)   ? __expf(fmaf(al, va[0], -mm)) : 0.0f,
                (f & 2u)   ? __expf(fmaf(al, va[1], -mm)) : 0.0f);
            __half2 h1 = __floats2half2_rn(
                (f & 4u)   ? __expf(fmaf(al, va[2], -mm)) : 0.0f,
                (f & 8u)   ? __expf(fmaf(al, va[3], -mm)) : 0.0f);
            __half2 h2 = __floats2half2_rn(
                (f & 16u)  ? __expf(fmaf(al, va[4], -mm)) : 0.0f,
                (f & 32u)  ? __expf(fmaf(al, va[5], -mm)) : 0.0f);
            __half2 h3 = __floats2half2_rn(
                (f & 64u)  ? __expf(fmaf(al, va[6], -mm)) : 0.0f,
                (f & 128u) ? __expf(fmaf(al, va[7], -mm)) : 0.0f);
            uint4 v = make_uint4(*(unsigned*)&h0, *(unsigned*)&h1,
                                 *(unsigned*)&h2, *(unsigned*)&h3);
            *(uint4*)(g_P + ((size_t)h * NN + i) * NN + j0) = v;
        }
    } else {
        // ================= xl16: x@W+b -> XT[h][c][j] ============
        unsigned* sAu = (unsigned*)smem_raw;               // [128][18]
        unsigned* sBu = (unsigned*)(smem_raw + 9216);      // [64][18]
        __half*   sBh = (__half*)sBu;
        int bb = blockIdx.x - 8192;
        int h = bb & 7;
        int m0 = (bb >> 3) * 128;
        int warp = tid >> 5, lane = tid & 31;
        int gid = lane >> 2, tig = lane & 3;
        int mw = warp & 3, nw = warp >> 2;

        float acc[2][4][4];
#pragma unroll
        for (int mi = 0; mi < 2; mi++)
#pragma unroll
            for (int ni = 0; ni < 4; ni++)
#pragma unroll
                for (int q = 0; q < 4; q++) acc[mi][ni][q] = 0.0f;

        for (int k0 = 0; k0 < NF; k0 += 32) {
#pragma unroll
            for (int q = 0; q < 8; q++) {
                int u = q * 256 + tid;
                int r = u >> 4, cp = u & 15;
                float2 v = *(const float2*)(x + (size_t)(m0 + r) * NF + k0 + 2 * cp);
                __half2 hh = __floats2half2_rn(v.x, v.y);
                sAu[r * 18 + cp] = *(unsigned*)&hh;
            }
#pragma unroll
            for (int q = 0; q < 8; q++) {
                int idx = q * 256 + tid;
                int r = idx >> 6, c = idx & 63;
                float v = W[(size_t)(k0 + r) * HC + h * NC + c];
                sBh[c * 36 + r] = __float2half(v);
            }
            __syncthreads();
#pragma unroll
            for (int ki = 0; ki < 2; ki++) {
                unsigned af[2][4];
#pragma unroll
                for (int mi = 0; mi < 2; mi++) {
                    int r0 = mw * 32 + mi * 16 + gid;
                    af[mi][0] = sAu[(r0)     * 18 + ki * 8 + tig];
                    af[mi][1] = sAu[(r0 + 8) * 18 + ki * 8 + tig];
                    af[mi][2] = sAu[(r0)     * 18 + ki * 8 + tig + 4];
                    af[mi][3] = sAu[(r0 + 8) * 18 + ki * 8 + tig + 4];
                }
#pragma unroll
                for (int ni = 0; ni < 4; ni++) {
                    int n = nw * 32 + ni * 8 + gid;
                    unsigned b0 = sBu[n * 18 + ki * 8 + tig];
                    unsigned b1 = sBu[n * 18 + ki * 8 + tig + 4];
#pragma unroll
                    for (int mi = 0; mi < 2; mi++) {
                        asm volatile(
                            "mma.sync.aligned.m16n8k16.row.col.f32.f16.f16.f32 "
                            "{%0,%1,%2,%3}, {%4,%5,%6,%7}, {%8,%9}, {%0,%1,%2,%3};\n"
                            : "+f"(acc[mi][ni][0]), "+f"(acc[mi][ni][1]),
                              "+f"(acc[mi][ni][2]), "+f"(acc[mi][ni][3])
                            : "r"(af[mi][0]), "r"(af[mi][1]),
                              "r"(af[mi][2]), "r"(af[mi][3]),
                              "r"(b0), "r"(b1));
                    }
                }
            }
            __syncthreads();
        }
        // epilogue: + bias, write TRANSPOSED into g_XT[h][c][j]
        __half* XTh = g_XT + (size_t)h * TC * NN;
#pragma unroll
        for (int mi = 0; mi < 2; mi++)
#pragma unroll
            for (int ni = 0; ni < 4; ni++) {
                int r0 = m0 + mw * 32 + mi * 16 + gid;
                int cc = nw * 32 + ni * 8 + tig * 2;
                float b0 = g_blb[h * NC + cc];
                float b1 = g_blb[h * NC + cc + 1];
                XTh[(size_t)(cc)     * NN + r0]     = __float2half(acc[mi][ni][0] + b0);
                XTh[(size_t)(cc + 1) * NN + r0]     = __float2half(acc[mi][ni][1] + b1);
                XTh[(size_t)(cc)     * NN + r0 + 8] = __float2half(acc[mi][ni][2] + b0);
                XTh[(size_t)(cc + 1) * NN + r0 + 8] = __float2half(acc[mi][ni][3] + b1);
            }
    }
}

// =================================================================
// K4: per head: C = P_h @ XT_h^T via fp16 MMA; epilogue normalize.
// grid (64, 8), 256 thr (4 m-warps x 2 n-warps), MT=64, KT=64
// =================================================================
__global__ void __launch_bounds__(256) k_agg(float* __restrict__ out) {
    __shared__ __align__(16) unsigned char smem_raw[19584];
    unsigned* sA  = (unsigned*)smem_raw;               // [64][36]
    unsigned* sBu = (unsigned*)(smem_raw + 9216);      // [72][36]
    float*    Cs  = (float*)smem_raw;                  // [64][73]

    int h = blockIdx.y;
    int i0 = blockIdx.x * 64;
    int tid = threadIdx.x;
    int warp = tid >> 5, lane = tid & 31;
    int gid = lane >> 2, tig = lane & 3;
    int mw = warp & 3, nw = warp >> 2;

    const __half* Ph = g_P + (size_t)h * NN * NN;
    const unsigned* XTu = (const unsigned*)(g_XT + (size_t)h * TC * NN);

    float acc[5][4];
#pragma unroll
    for (int ni = 0; ni < 5; ni++)
#pragma unroll
        for (int q = 0; q < 4; q++) acc[ni][q] = 0.0f;

    for (int k0 = 0; k0 < NN; k0 += 64) {
        // A tile: 64 rows x 64 halfs, coalesced uint4
#pragma unroll
        for (int q = 0; q < 2; q++) {
            int idx = q * 256 + tid;
            int r = idx >> 3, c4 = idx & 7;
            uint4 v = *(const uint4*)(Ph + (size_t)(i0 + r) * NN + k0 + c4 * 8);
            *(uint4*)&sA[r * 36 + c4 * 4] = v;
        }
        // B tile: XT rows 0..71, 32 uints each, direct copy
#pragma unroll
        for (int q = 0; q < 9; q++) {
            int idx = q * 256 + tid;
            int r = idx >> 5, cu = idx & 31;
            sBu[r * 36 + cu] = XTu[(size_t)r * (NN / 2) + (k0 >> 1) + cu];
        }
        __syncthreads();
#pragma unroll
        for (int ki = 0; ki < 4; ki++) {
            unsigned afr[4];
            int r0 = mw * 16 + gid;
            afr[0] = sA[(r0)     * 36 + ki * 8 + tig];
            afr[1] = sA[(r0 + 8) * 36 + ki * 8 + tig];
            afr[2] = sA[(r0)     * 36 + ki * 8 + tig + 4];
            afr[3] = sA[(r0 + 8) * 36 + ki * 8 + tig + 4];
#pragma unroll
            for (int ni = 0; ni < 5; ni++) {
                if (!(nw == 1 && ni == 4)) {
                    int n = nw * 40 + ni * 8 + gid;
                    unsigned b0 = sBu[n * 36 + ki * 8 + tig];
                    unsigned b1 = sBu[n * 36 + ki * 8 + tig + 4];
                    asm volatile(
                        "mma.sync.aligned.m16n8k16.row.col.f32.f16.f16.f32 "
                        "{%0,%1,%2,%3}, {%4,%5,%6,%7}, {%8,%9}, {%0,%1,%2,%3};\n"
                        : "+f"(acc[ni][0]), "+f"(acc[ni][1]),
                          "+f"(acc[ni][2]), "+f"(acc[ni][3])
                        : "r"(afr[0]), "r"(afr[1]), "r"(afr[2]), "r"(afr[3]),
                          "r"(b0), "r"(b1));
                }
            }
        }
        __syncthreads();
    }

#pragma unroll
    for (int ni = 0; ni < 5; ni++) {
        if (!(nw == 1 && ni == 4)) {
            int r0 = mw * 16 + gid;
            int cc = nw * 40 + ni * 8 + tig * 2;
            Cs[(r0)     * 73 + cc]     = acc[ni][0];
            Cs[(r0)     * 73 + cc + 1] = acc[ni][1];
            Cs[(r0 + 8) * 73 + cc]     = acc[ni][2];
            Cs[(r0 + 8) * 73 + cc + 1] = acc[ni][3];
        }
    }
    __syncthreads();
#pragma unroll
    for (int q = 0; q < 16; q++) {
        int idx = q * 256 + tid;
        int r = idx >> 6, c = idx & 63;
        float z = Cs[r * 73 + 64];
        float v = Cs[r * 73 + c];
        v = (z > 0.0f) ? (v / z) : 0.0f;
        out[(size_t)(i0 + r) * HC + h * NC + c] = fmaxf(v, 0.0f);
    }
}

// =================================================================
extern "C" void kernel_launch(void* const* d_in, const int* in_sizes, int n_in,
                              void* d_out, int out_size) {
    const float* x     = (const float*)d_in[0];
    const int*   adj   = (const int*)d_in[1];
    const float* W     = (const float*)d_in[2];
    const float* b     = (const float*)d_in[3];
    const float* att_l = (const float*)d_in[4];
    const float* att_r = (const float*)d_in[5];
    float* out = (float*)d_out;

    k_prep<<<4641, 256>>>(adj, W, b, att_l, att_r);
    k_alpha<<<NN, 256>>>(x);
    k_mid<<<8448, 256>>>(x, W);
    k_agg<<<dim3(NN / 64, NH), 256>>>(out);
}

// round 7
// speedup vs baseline: 1.7395x; 1.0996x over previous
#include <cuda_runtime.h>
#include <cuda_fp16.h>
#include <cuda_bf16.h>
#include <math.h>

#define NN 4096
#define NF 512
#define NH 8
#define NC 64
#define HC 512
#define TC 72

// -------- scratch --------
__device__ float    g_wl[NH * NF], g_wr[NH * NF];
__device__ float    g_bl[NH], g_br[NH];
__device__ float    g_blb[HC];                      // bias copy for xl16 epilogue
__device__ float    g_alT[NH * NN];                 // alpha_l [h][n]
__device__ float    g_arT[NH * NN];                 // alpha_r [h][n]
__device__ unsigned g_rmaxu[NH], g_rminu[NH];       // monotone-coded stats
__device__ __half   g_XT[(size_t)NH * TC * NN];     // X-tilde TRANSPOSED [h][c][j]
__device__ unsigned g_adjbits[(size_t)NN * 128];    // adj bitmask, 2MB

__device__ __forceinline__ unsigned fmono(float f) {
    unsigned u = __float_as_uint(f);
    return (u & 0x80000000u) ? ~u : (u | 0x80000000u);
}
__device__ __forceinline__ float fdec(unsigned u) {
    return __uint_as_float((u & 0x80000000u) ? (u ^ 0x80000000u) : ~u);
}
__device__ __forceinline__ void cp16(void* dst, const void* src) {
    unsigned d = (unsigned)__cvta_generic_to_shared(dst);
    asm volatile("cp.async.cg.shared.global [%0], [%1], 16;\n" :: "r"(d), "l"(src));
}

// =================================================================
// K1: pack adj | prepw | XT tail rows | stat init | bias copy
// =================================================================
__global__ void __launch_bounds__(256) k_prep(const int* __restrict__ adj,
                                              const float* __restrict__ W,
                                              const float* __restrict__ b,
                                              const float* __restrict__ attl,
                                              const float* __restrict__ attr) {
    int bb = blockIdx.x, tid = threadIdx.x;
    if (bb < 4096) {                    // ---- pack one adj row ----
        int warp = tid >> 5, lane = tid & 31;
        const int* row = adj + (size_t)bb * NN;
#pragma unroll
        for (int w = warp; w < 128; w += 8) {
            int v = __ldg(&row[w * 32 + lane]);
            unsigned m = __ballot_sync(0xFFFFFFFFu, v > 0);
            if (lane == 0) g_adjbits[bb * 128 + w] = m;
        }
    } else if (bb < 4128) {             // ---- prepw ----
        int idx = (bb - 4096) * 256 + tid;      // 0..8191
        int side = idx >> 12;
        int h = (idx >> 9) & 7;
        int k = idx & 511;
        const float* av = (side ? attr : attl) + h * NC;
        const float* wr = W + (size_t)k * HC + h * NC;
        float s = 0.0f;
#pragma unroll
        for (int c = 0; c < NC; c++) s = fmaf(wr[c], av[c], s);
        (side ? g_wr : g_wl)[h * NF + k] = s;
        if (idx < 16) {
            int sd = idx >> 3, hh = idx & 7;
            const float* av2 = (sd ? attr : attl) + hh * NC;
            float s2 = 0.0f;
#pragma unroll
            for (int c = 0; c < NC; c++) s2 = fmaf(b[hh * NC + c], av2[c], s2);
            (sd ? g_br : g_bl)[hh] = s2;
        }
        if (bb == 4096) {               // bias copy (512 floats)
            g_blb[tid] = b[tid];
            g_blb[tid + 256] = b[tid + 256];
        }
    } else if (bb < 4640) {             // ---- XT tail rows: c=64 ones, 65..71 zero ----
        int idx = (bb - 4128) * 256 + tid;      // 0..131071 uints
        int h = idx >> 14;
        int rem = idx & 16383;
        int c = 64 + (rem >> 11);
        int ju = rem & 2047;
        ((unsigned*)g_XT)[((size_t)h * TC + c) * (NN / 2) + ju] =
            (c == 64) ? 0x3C003C00u : 0u;
    } else {                            // ---- stat init ----
        if (tid < NH) { g_rmaxu[tid] = 0u; g_rminu[tid] = 0xFFFFFFFFu; }
    }
}

// =================================================================
// K2: exact fp32 alphas + atomic per-head max/min of alpha_r
// =================================================================
__global__ void __launch_bounds__(256) k_alpha(const float* __restrict__ x) {
    __shared__ float sx[NF];
    int n = blockIdx.x;
    int tid = threadIdx.x;
    sx[tid]       = x[(size_t)n * NF + tid];
    sx[tid + 256] = x[(size_t)n * NF + tid + 256];
    __syncthreads();
    int w = tid >> 5, lane = tid & 31;
    float sl = 0.0f, sr = 0.0f;
#pragma unroll
    for (int i = 0; i < 16; i++) {
        float xv = sx[lane + 32 * i];
        sl = fmaf(xv, g_wl[w * NF + lane + 32 * i], sl);
        sr = fmaf(xv, g_wr[w * NF + lane + 32 * i], sr);
    }
#pragma unroll
    for (int o = 16; o; o >>= 1) {
        sl += __shfl_xor_sync(0xFFFFFFFFu, sl, o);
        sr += __shfl_xor_sync(0xFFFFFFFFu, sr, o);
    }
    if (lane == 0) {
        float vr = sr + g_br[w];
        g_alT[w * NN + n] = sl + g_bl[w];
        g_arT[w * NN + n] = vr;
        unsigned um = fmono(vr);
        atomicMax(&g_rmaxu[w], um);
        atomicMin(&g_rminu[w], um);
    }
}

// =================================================================
// K3: xl16: x@W+b (fp16 MMA) -> XT[h][c][j] transposed
// =================================================================
__global__ void __launch_bounds__(256) k_xl16(const float* __restrict__ x,
                                              const float* __restrict__ W) {
    __shared__ __align__(16) unsigned sAu[128 * 18];
    __shared__ __align__(16) unsigned sBu[64 * 18];
    __half* sBh = (__half*)sBu;
    int bb = blockIdx.x;
    int h = bb & 7;
    int m0 = (bb >> 3) * 128;
    int tid = threadIdx.x;
    int warp = tid >> 5, lane = tid & 31;
    int gid = lane >> 2, tig = lane & 3;
    int mw = warp & 3, nw = warp >> 2;

    float acc[2][4][4];
#pragma unroll
    for (int mi = 0; mi < 2; mi++)
#pragma unroll
        for (int ni = 0; ni < 4; ni++)
#pragma unroll
            for (int q = 0; q < 4; q++) acc[mi][ni][q] = 0.0f;

    for (int k0 = 0; k0 < NF; k0 += 32) {
#pragma unroll
        for (int q = 0; q < 8; q++) {
            int u = q * 256 + tid;
            int r = u >> 4, cp = u & 15;
            float2 v = *(const float2*)(x + (size_t)(m0 + r) * NF + k0 + 2 * cp);
            __half2 hh = __floats2half2_rn(v.x, v.y);
            sAu[r * 18 + cp] = *(unsigned*)&hh;
        }
#pragma unroll
        for (int q = 0; q < 8; q++) {
            int idx = q * 256 + tid;
            int r = idx >> 6, c = idx & 63;
            float v = W[(size_t)(k0 + r) * HC + h * NC + c];
            sBh[c * 36 + r] = __float2half(v);
        }
        __syncthreads();
#pragma unroll
        for (int ki = 0; ki < 2; ki++) {
            unsigned af[2][4];
#pragma unroll
            for (int mi = 0; mi < 2; mi++) {
                int r0 = mw * 32 + mi * 16 + gid;
                af[mi][0] = sAu[(r0)     * 18 + ki * 8 + tig];
                af[mi][1] = sAu[(r0 + 8) * 18 + ki * 8 + tig];
                af[mi][2] = sAu[(r0)     * 18 + ki * 8 + tig + 4];
                af[mi][3] = sAu[(r0 + 8) * 18 + ki * 8 + tig + 4];
            }
#pragma unroll
            for (int ni = 0; ni < 4; ni++) {
                int n = nw * 32 + ni * 8 + gid;
                unsigned b0 = sBu[n * 18 + ki * 8 + tig];
                unsigned b1 = sBu[n * 18 + ki * 8 + tig + 4];
#pragma unroll
                for (int mi = 0; mi < 2; mi++) {
                    asm volatile(
                        "mma.sync.aligned.m16n8k16.row.col.f32.f16.f16.f32 "
                        "{%0,%1,%2,%3}, {%4,%5,%6,%7}, {%8,%9}, {%0,%1,%2,%3};\n"
                        : "+f"(acc[mi][ni][0]), "+f"(acc[mi][ni][1]),
                          "+f"(acc[mi][ni][2]), "+f"(acc[mi][ni][3])
                        : "r"(af[mi][0]), "r"(af[mi][1]),
                          "r"(af[mi][2]), "r"(af[mi][3]),
                          "r"(b0), "r"(b1));
                }
            }
        }
        __syncthreads();
    }
    __half* XTh = g_XT + (size_t)h * TC * NN;
#pragma unroll
    for (int mi = 0; mi < 2; mi++)
#pragma unroll
        for (int ni = 0; ni < 4; ni++) {
            int r0 = m0 + mw * 32 + mi * 16 + gid;
            int cc = nw * 32 + ni * 8 + tig * 2;
            float b0 = g_blb[h * NC + cc];
            float b1 = g_blb[h * NC + cc + 1];
            XTh[(size_t)(cc)     * NN + r0]     = __float2half(acc[mi][ni][0] + b0);
            XTh[(size_t)(cc + 1) * NN + r0]     = __float2half(acc[mi][ni][1] + b1);
            XTh[(size_t)(cc)     * NN + r0 + 8] = __float2half(acc[mi][ni][2] + b0);
            XTh[(size_t)(cc + 1) * NN + r0 + 8] = __float2half(acc[mi][ni][3] + b1);
        }
}

// =================================================================
// K4: FUSED pipelined aggregation. Per (i-block, head):
//   A(k) = P tile built in smem from adj bits + alphas (exp, fp16)
//   B(k) = XT tile via cp.async (L2-resident)
//   2-stage double buffer: build/load k+1 before waiting on k.
// Epilogue: out = relu(C[:, :64] / C[:, 64]).
// =================================================================
#define MT 64
#define KT 64
#define SA_U 2304      // 64*36 uints per A buffer
#define SB_U 2592      // 72*36 uints per B buffer
__global__ void __launch_bounds__(256) k_aggF2(float* __restrict__ out) {
    // [0, 18432) sA x2 | [18432, 39168) sB x2 ; epilogue Cs overlays
    __shared__ __align__(16) unsigned char smem_raw[39168];
    unsigned* sA  = (unsigned*)smem_raw;
    unsigned* sBu = (unsigned*)(smem_raw + 18432);
    float*    Cs  = (float*)smem_raw;                  // [64][73]

    int h = blockIdx.y;
    int i0 = blockIdx.x * MT;
    int tid = threadIdx.x;
    int warp = tid >> 5, lane = tid & 31;
    int gid = lane >> 2, tig = lane & 3;
    int mw = warp & 3, nw = warp >> 2;

    // ---- A-build role: row = tid>>2, 16-col quad = tid&3 ----
    int arow = tid >> 2;
    int q4 = tid & 3;
    float al, mm;
    {
        float rmx = fdec(g_rmaxu[h]), rmn = fdec(g_rminu[h]);
        al = g_alT[h * NN + i0 + arow];
        mm = (al >= 0.0f) ? al * rmx : al * rmn;
    }
    const unsigned* bits_row = g_adjbits + (size_t)(i0 + arow) * 128 + (q4 >> 1);
    int shbase = (q4 & 1) * 16;
    const float* arp_base = g_arT + h * NN + q4 * 16;
    const unsigned* XTu = (const unsigned*)(g_XT + (size_t)h * TC * NN);

    // B cp.async role: chunks c -> (row=c/8, cu=c%8)
    int br0 = tid >> 3,          bc0 = tid & 7;         // c = tid
    int br1 = (tid + 256) >> 3,  bc1 = bc0;             // c = tid+256
    int br2 = (tid + 512) >> 3,  bc2 = bc0;             // c = tid+512 (guard < 576)

    float acc[5][4];
#pragma unroll
    for (int ni = 0; ni < 5; ni++)
#pragma unroll
        for (int q = 0; q < 4; q++) acc[ni][q] = 0.0f;

#define BUILD_A(IT, BUF) do {                                              \
    int k0_ = (IT) * KT;                                                   \
    unsigned wb_ = __ldg(&bits_row[k0_ >> 5]);                             \
    unsigned f_ = (wb_ >> shbase) & 0xFFFFu;                               \
    const float4* arp_ = (const float4*)(arp_base + k0_);                  \
    unsigned* dst_ = sA + (BUF) * SA_U + arow * 36 + q4 * 8;               \
    _Pragma("unroll")                                                      \
    for (int q_ = 0; q_ < 4; q_++) {                                       \
        float4 v_ = __ldg(&arp_[q_]);                                      \
        unsigned fq_ = f_ >> (4 * q_);                                     \
        __half2 h0_ = __floats2half2_rn(                                   \
            (fq_ & 1u) ? __expf(fmaf(al, v_.x, -mm)) : 0.0f,               \
            (fq_ & 2u) ? __expf(fmaf(al, v_.y, -mm)) : 0.0f);              \
        __half2 h1_ = __floats2half2_rn(                                   \
            (fq_ & 4u) ? __expf(fmaf(al, v_.z, -mm)) : 0.0f,               \
            (fq_ & 8u) ? __expf(fmaf(al, v_.w, -mm)) : 0.0f);              \
        dst_[2 * q_]     = *(unsigned*)&h0_;                               \
        dst_[2 * q_ + 1] = *(unsigned*)&h1_;                               \
    }                                                                      \
} while (0)

#define LOAD_B(IT, BUF) do {                                               \
    int ku_ = (IT) * (KT / 2);                                             \
    unsigned* db_ = sBu + (BUF) * SB_U;                                    \
    cp16(&db_[br0 * 36 + bc0 * 4], &XTu[(size_t)br0 * (NN / 2) + ku_ + bc0 * 4]); \
    cp16(&db_[br1 * 36 + bc1 * 4], &XTu[(size_t)br1 * (NN / 2) + ku_ + bc1 * 4]); \
    if (tid < 64)                                                          \
        cp16(&db_[br2 * 36 + bc2 * 4], &XTu[(size_t)br2 * (NN / 2) + ku_ + bc2 * 4]); \
    asm volatile("cp.async.commit_group;\n" ::: "memory");                 \
} while (0)

    // prologue
    BUILD_A(0, 0);
    LOAD_B(0, 0);

    for (int it = 0; it < NN / KT; it++) {
        int buf = it & 1;
        if (it < NN / KT - 1) {
            BUILD_A(it + 1, buf ^ 1);
            LOAD_B(it + 1, buf ^ 1);
            asm volatile("cp.async.wait_group 1;\n" ::: "memory");
        } else {
            asm volatile("cp.async.wait_group 0;\n" ::: "memory");
        }
        __syncthreads();

        unsigned* sAb = sA + buf * SA_U;
        unsigned* sBb = sBu + buf * SB_U;
#pragma unroll
        for (int ki = 0; ki < 4; ki++) {
            unsigned afr[4];
            int r0 = mw * 16 + gid;
            afr[0] = sAb[(r0)     * 36 + ki * 8 + tig];
            afr[1] = sAb[(r0 + 8) * 36 + ki * 8 + tig];
            afr[2] = sAb[(r0)     * 36 + ki * 8 + tig + 4];
            afr[3] = sAb[(r0 + 8) * 36 + ki * 8 + tig + 4];
#pragma unroll
            for (int ni = 0; ni < 5; ni++) {
                if (!(nw == 1 && ni == 4)) {
                    int n = nw * 40 + ni * 8 + gid;
                    unsigned b0 = sBb[n * 36 + ki * 8 + tig];
                    unsigned b1 = sBb[n * 36 + ki * 8 + tig + 4];
                    asm volatile(
                        "mma.sync.aligned.m16n8k16.row.col.f32.f16.f16.f32 "
                        "{%0,%1,%2,%3}, {%4,%5,%6,%7}, {%8,%9}, {%0,%1,%2,%3};\n"
                        : "+f"(acc[ni][0]), "+f"(acc[ni][1]),
                          "+f"(acc[ni][2]), "+f"(acc[ni][3])
                        : "r"(afr[0]), "r"(afr[1]), "r"(afr[2]), "r"(afr[3]),
                          "r"(b0), "r"(b1));
                }
            }
        }
        __syncthreads();
    }

    // ---- epilogue: dump, normalize by ones-column, relu, store ----
#pragma unroll
    for (int ni = 0; ni < 5; ni++) {
        if (!(nw == 1 && ni == 4)) {
            int r0 = mw * 16 + gid;
            int cc = nw * 40 + ni * 8 + tig * 2;
            Cs[(r0)     * 73 + cc]     = acc[ni][0];
            Cs[(r0)     * 73 + cc + 1] = acc[ni][1];
            Cs[(r0 + 8) * 73 + cc]     = acc[ni][2];
            Cs[(r0 + 8) * 73 + cc + 1] = acc[ni][3];
        }
    }
    __syncthreads();
#pragma unroll
    for (int q = 0; q < 16; q++) {
        int idx = q * 256 + tid;
        int r = idx >> 6, c = idx & 63;
        float z = Cs[r * 73 + 64];
        float v = Cs[r * 73 + c];
        v = (z > 0.0f) ? (v / z) : 0.0f;
        out[(size_t)(i0 + r) * HC + h * NC + c] = fmaxf(v, 0.0f);
    }
}

// =================================================================
extern "C" void kernel_launch(void* const* d_in, const int* in_sizes, int n_in,
                              void* d_out, int out_size) {
    const float* x     = (const float*)d_in[0];
    const int*   adj   = (const int*)d_in[1];
    const float* W     = (const float*)d_in[2];
    const float* b     = (const float*)d_in[3];
    const float* att_l = (const float*)d_in[4];
    const float* att_r = (const float*)d_in[5];
    float* out = (float*)d_out;

    k_prep<<<4641, 256>>>(adj, W, b, att_l, att_r);
    k_alpha<<<NN, 256>>>(x);
    k_xl16<<<NN / 128 * NH, 256>>>(x, W);
    k_aggF2<<<dim3(NN / MT, NH), 256>>>(out);
}

// round 10
// speedup vs baseline: 2.5551x; 1.4689x over previous
#include <cuda_runtime.h>
#include <cuda_fp16.h>
#include <cuda_bf16.h>
#include <math.h>
#include <stdint.h>

#define NN 4096
#define NF 512
#define NH 8
#define NC 64
#define HC 512
#define TC 72

// -------- scratch --------
__device__ float    g_wl[NH * NF], g_wr[NH * NF];
__device__ float    g_bl[NH], g_br[NH];
__device__ float    g_blb[HC];
__device__ float    g_alT[NH * NN];                 // alpha_l [h][n]
__device__ float    g_arT[NH * NN];                 // alpha_r [h][n]
__device__ unsigned g_rmaxu[NH], g_rminu[NH];
__device__ __half   g_XT[(size_t)NH * TC * NN];     // X-tilde transposed [h][c][j]
__device__ unsigned g_adjbits[(size_t)NN * 128];    // adj bitmask, 2MB

__device__ __forceinline__ unsigned fmono(float f) {
    unsigned u = __float_as_uint(f);
    return (u & 0x80000000u) ? ~u : (u | 0x80000000u);
}
__device__ __forceinline__ float fdec(unsigned u) {
    return __uint_as_float((u & 0x80000000u) ? (u ^ 0x80000000u) : ~u);
}
__device__ __forceinline__ uint32_t s2u(const void* p) {
    uint32_t a;
    asm("{ .reg .u64 t; cvta.to.shared.u64 t, %1; cvt.u32.u64 %0, t; }" : "=r"(a) : "l"(p));
    return a;
}
__device__ __forceinline__ float ex2f(float x) {
    float y; asm("ex2.approx.ftz.f32 %0, %1;" : "=f"(y) : "f"(x)); return y;
}
__device__ __forceinline__ void cp16(void* dst, const void* src) {
    unsigned d = (unsigned)__cvta_generic_to_shared(dst);
    asm volatile("cp.async.cg.shared.global [%0], [%1], 16;\n" :: "r"(d), "l"(src));
}
__device__ __forceinline__ void ldsm4(uint32_t& r0, uint32_t& r1, uint32_t& r2,
                                      uint32_t& r3, uint32_t a) {
    asm volatile("ldmatrix.sync.aligned.m8n8.x4.shared.b16 {%0,%1,%2,%3}, [%4];"
                 : "=r"(r0), "=r"(r1), "=r"(r2), "=r"(r3) : "r"(a));
}
__device__ __forceinline__ void ldsm2(uint32_t& r0, uint32_t& r1, uint32_t a) {
    asm volatile("ldmatrix.sync.aligned.m8n8.x2.shared.b16 {%0,%1}, [%2];"
                 : "=r"(r0), "=r"(r1) : "r"(a));
}
#define HMMA(ACC, A0, A1, A2, A3, B0, B1)                                   \
    asm volatile(                                                           \
        "mma.sync.aligned.m16n8k16.row.col.f32.f16.f16.f32 "                \
        "{%0,%1,%2,%3}, {%4,%5,%6,%7}, {%8,%9}, {%0,%1,%2,%3};\n"           \
        : "+f"((ACC)[0]), "+f"((ACC)[1]), "+f"((ACC)[2]), "+f"((ACC)[3])    \
        : "r"(A0), "r"(A1), "r"(A2), "r"(A3), "r"(B0), "r"(B1))

// =================================================================
// K1: pack adj | prepw | XT tail rows | stat init | bias copy
// =================================================================
__global__ void __launch_bounds__(256) k_prep(const int* __restrict__ adj,
                                              const float* __restrict__ W,
                                              const float* __restrict__ b,
                                              const float* __restrict__ attl,
                                              const float* __restrict__ attr) {
    int bb = blockIdx.x, tid = threadIdx.x;
    if (bb < 4096) {
        int warp = tid >> 5, lane = tid & 31;
        const int* row = adj + (size_t)bb * NN;
#pragma unroll
        for (int w = warp; w < 128; w += 8) {
            int v = __ldg(&row[w * 32 + lane]);
            unsigned m = __ballot_sync(0xFFFFFFFFu, v > 0);
            if (lane == 0) g_adjbits[bb * 128 + w] = m;
        }
    } else if (bb < 4128) {
        int idx = (bb - 4096) * 256 + tid;
        int side = idx >> 12;
        int h = (idx >> 9) & 7;
        int k = idx & 511;
        const float* av = (side ? attr : attl) + h * NC;
        const float* wr = W + (size_t)k * HC + h * NC;
        float s = 0.0f;
#pragma unroll
        for (int c = 0; c < NC; c++) s = fmaf(wr[c], av[c], s);
        (side ? g_wr : g_wl)[h * NF + k] = s;
        if (idx < 16) {
            int sd = idx >> 3, hh = idx & 7;
            const float* av2 = (sd ? attr : attl) + hh * NC;
            float s2 = 0.0f;
#pragma unroll
            for (int c = 0; c < NC; c++) s2 = fmaf(b[hh * NC + c], av2[c], s2);
            (sd ? g_br : g_bl)[hh] = s2;
        }
        if (bb == 4096) {
            g_blb[tid] = b[tid];
            g_blb[tid + 256] = b[tid + 256];
        }
    } else if (bb < 4640) {
        int idx = (bb - 4128) * 256 + tid;
        int h = idx >> 14;
        int rem = idx & 16383;
        int c = 64 + (rem >> 11);
        int ju = rem & 2047;
        ((unsigned*)g_XT)[((size_t)h * TC + c) * (NN / 2) + ju] =
            (c == 64) ? 0x3C003C00u : 0u;
    } else {
        if (tid < NH) { g_rmaxu[tid] = 0u; g_rminu[tid] = 0xFFFFFFFFu; }
    }
}

// =================================================================
// K2: exact fp32 alphas + atomic per-head max/min of alpha_r
// =================================================================
__global__ void __launch_bounds__(256) k_alpha(const float* __restrict__ x) {
    __shared__ float sx[NF];
    int n = blockIdx.x;
    int tid = threadIdx.x;
    sx[tid]       = x[(size_t)n * NF + tid];
    sx[tid + 256] = x[(size_t)n * NF + tid + 256];
    __syncthreads();
    int w = tid >> 5, lane = tid & 31;
    float sl = 0.0f, sr = 0.0f;
#pragma unroll
    for (int i = 0; i < 16; i++) {
        float xv = sx[lane + 32 * i];
        sl = fmaf(xv, g_wl[w * NF + lane + 32 * i], sl);
        sr = fmaf(xv, g_wr[w * NF + lane + 32 * i], sr);
    }
#pragma unroll
    for (int o = 16; o; o >>= 1) {
        sl += __shfl_xor_sync(0xFFFFFFFFu, sl, o);
        sr += __shfl_xor_sync(0xFFFFFFFFu, sr, o);
    }
    if (lane == 0) {
        float vr = sr + g_br[w];
        g_alT[w * NN + n] = sl + g_bl[w];
        g_arT[w * NN + n] = vr;
        unsigned um = fmono(vr);
        atomicMax(&g_rmaxu[w], um);
        atomicMin(&g_rminu[w], um);
    }
}

// =================================================================
// K3: xl16: x@W+b (fp16 MMA) -> XT[h][c][j] transposed
// =================================================================
__global__ void __launch_bounds__(256) k_xl16(const float* __restrict__ x,
                                              const float* __restrict__ W) {
    __shared__ __align__(16) unsigned sAu[128 * 18];
    __shared__ __align__(16) unsigned sBu[64 * 18];
    __half* sBh = (__half*)sBu;
    int bb = blockIdx.x;
    int h = bb & 7;
    int m0 = (bb >> 3) * 128;
    int tid = threadIdx.x;
    int warp = tid >> 5, lane = tid & 31;
    int gid = lane >> 2, tig = lane & 3;
    int mw = warp & 3, nw = warp >> 2;

    float acc[2][4][4];
#pragma unroll
    for (int mi = 0; mi < 2; mi++)
#pragma unroll
        for (int ni = 0; ni < 4; ni++)
#pragma unroll
            for (int q = 0; q < 4; q++) acc[mi][ni][q] = 0.0f;

    for (int k0 = 0; k0 < NF; k0 += 32) {
#pragma unroll
        for (int q = 0; q < 8; q++) {
            int u = q * 256 + tid;
            int r = u >> 4, cp = u & 15;
            float2 v = *(const float2*)(x + (size_t)(m0 + r) * NF + k0 + 2 * cp);
            __half2 hh = __floats2half2_rn(v.x, v.y);
            sAu[r * 18 + cp] = *(unsigned*)&hh;
        }
#pragma unroll
        for (int q = 0; q < 8; q++) {
            int idx = q * 256 + tid;
            int r = idx >> 6, c = idx & 63;
            float v = W[(size_t)(k0 + r) * HC + h * NC + c];
            sBh[c * 36 + r] = __float2half(v);
        }
        __syncthreads();
#pragma unroll
        for (int ki = 0; ki < 2; ki++) {
            unsigned af[2][4];
#pragma unroll
            for (int mi = 0; mi < 2; mi++) {
                int r0 = mw * 32 + mi * 16 + gid;
                af[mi][0] = sAu[(r0)     * 18 + ki * 8 + tig];
                af[mi][1] = sAu[(r0 + 8) * 18 + ki * 8 + tig];
                af[mi][2] = sAu[(r0)     * 18 + ki * 8 + tig + 4];
                af[mi][3] = sAu[(r0 + 8) * 18 + ki * 8 + tig + 4];
            }
#pragma unroll
            for (int ni = 0; ni < 4; ni++) {
                int n = nw * 32 + ni * 8 + gid;
                unsigned b0 = sBu[n * 18 + ki * 8 + tig];
                unsigned b1 = sBu[n * 18 + ki * 8 + tig + 4];
#pragma unroll
                for (int mi = 0; mi < 2; mi++) {
                    asm volatile(
                        "mma.sync.aligned.m16n8k16.row.col.f32.f16.f16.f32 "
                        "{%0,%1,%2,%3}, {%4,%5,%6,%7}, {%8,%9}, {%0,%1,%2,%3};\n"
                        : "+f"(acc[mi][ni][0]), "+f"(acc[mi][ni][1]),
                          "+f"(acc[mi][ni][2]), "+f"(acc[mi][ni][3])
                        : "r"(af[mi][0]), "r"(af[mi][1]),
                          "r"(af[mi][2]), "r"(af[mi][3]),
                          "r"(b0), "r"(b1));
                }
            }
        }
        __syncthreads();
    }
    __half* XTh = g_XT + (size_t)h * TC * NN;
#pragma unroll
    for (int mi = 0; mi < 2; mi++)
#pragma unroll
        for (int ni = 0; ni < 4; ni++) {
            int r0 = m0 + mw * 32 + mi * 16 + gid;
            int cc = nw * 32 + ni * 8 + tig * 2;
            float b0 = g_blb[h * NC + cc];
            float b1 = g_blb[h * NC + cc + 1];
            XTh[(size_t)(cc)     * NN + r0]     = __float2half(acc[mi][ni][0] + b0);
            XTh[(size_t)(cc + 1) * NN + r0]     = __float2half(acc[mi][ni][1] + b1);
            XTh[(size_t)(cc)     * NN + r0 + 8] = __float2half(acc[mi][ni][2] + b0);
            XTh[(size_t)(cc + 1) * NN + r0 + 8] = __float2half(acc[mi][ni][3] + b1);
        }
}

// =================================================================
// K4: fused aggregation v3 — ldmatrix fragments, alpha_r via L1/L2.
// grid (64, 8), 256 thr (4 m-warps x 2 n-warps), MT=64, KT=64.
// smem: A x2 (64 x 144B) | B x2 (72 x 144B)  = 39168 B  (< 48KB)
// =================================================================
#define SM_A0 0
#define SM_A1 9216
#define SM_B0 18432
#define SM_B1 28800
#define SM_TOT 39168
__global__ void __launch_bounds__(256) k_aggF3(float* __restrict__ out) {
    __shared__ __align__(16) unsigned char sm[SM_TOT];
    uint32_t smb = s2u(sm);
    float* Cs = (float*)sm;                     // epilogue overlay [64][73]

    int h = blockIdx.y;
    int i0 = blockIdx.x * 64;
    int tid = threadIdx.x;
    int warp = tid >> 5, lane = tid & 31;
    int gid = lane >> 2, tig = lane & 3;
    int mw = warp & 3, nw = warp >> 2;

    // ---- builder role: row r, 16-col group qq ----
    int r = tid >> 2, qq = tid & 3;
    float al2, nm2;
    {
        float rmx = fdec(g_rmaxu[h]), rmn = fdec(g_rminu[h]);
        float al = g_alT[h * NN + i0 + r];
        float mm = (al >= 0.0f) ? al * rmx : al * rmn;
        const float L2E = 1.4426950408889634f;
        al2 = al * L2E; nm2 = -mm * L2E;
    }
    const unsigned* bitsrow = g_adjbits + (size_t)(i0 + r) * 128 + (qq >> 1);
    int shb = (qq & 1) * 16;
    const float* arbase = g_arT + h * NN + qq * 16;   // L1/L2-resident (16KB/head)

    // ---- B cp.async roles (72 rows x 128B) ----
    const unsigned* XTu = (const unsigned*)(g_XT + (size_t)h * TC * NN);
    int br0 = tid >> 3,         bc = tid & 7;
    int br1 = (tid + 256) >> 3;
    int br2 = (tid + 512) >> 3;

    // ---- ldmatrix lane addresses (byte offsets in smem) ----
    uint32_t aA = smb + SM_A0 + (mw * 16 + (lane & 15)) * 144 + ((lane >> 4) & 1) * 16;
    int nbase = nw ? 40 : 0;
    uint32_t bA0 = smb + SM_B0 +
                   (nbase + (lane & 7) + ((lane >> 4) & 1) * 8) * 144 +
                   ((lane >> 3) & 1) * 16;
    uint32_t bA1 = bA0 + 16 * 144;
    uint32_t bA2 = smb + SM_B0 + (32 + (lane & 7)) * 144 + ((lane >> 3) & 1) * 16;

    float acc[5][4];
#pragma unroll
    for (int ni = 0; ni < 5; ni++)
#pragma unroll
        for (int q = 0; q < 4; q++) acc[ni][q] = 0.0f;

#define BUILD_A(IT, BUF) do {                                               \
    unsigned f_ = (__ldg(&bitsrow[(IT) * 2]) >> shb) & 0xFFFFu;             \
    const float4* ap_ = (const float4*)(arbase + (IT) * 64);                \
    unsigned* dst_ = (unsigned*)(sm + ((BUF) ? SM_A1 : SM_A0)) + r * 36 + qq * 8; \
    _Pragma("unroll")                                                       \
    for (int g_ = 0; g_ < 2; g_++) {                                        \
        float4 v0_ = __ldg(&ap_[2 * g_]);                                   \
        float4 v1_ = __ldg(&ap_[2 * g_ + 1]);                               \
        unsigned fg_ = f_ >> (8 * g_);                                      \
        float e0 = ex2f((fg_ & 1u)   ? fmaf(al2, v0_.x, nm2) : -200.0f);    \
        float e1 = ex2f((fg_ & 2u)   ? fmaf(al2, v0_.y, nm2) : -200.0f);    \
        float e2 = ex2f((fg_ & 4u)   ? fmaf(al2, v0_.z, nm2) : -200.0f);    \
        float e3 = ex2f((fg_ & 8u)   ? fmaf(al2, v0_.w, nm2) : -200.0f);    \
        float e4 = ex2f((fg_ & 16u)  ? fmaf(al2, v1_.x, nm2) : -200.0f);    \
        float e5 = ex2f((fg_ & 32u)  ? fmaf(al2, v1_.y, nm2) : -200.0f);    \
        float e6 = ex2f((fg_ & 64u)  ? fmaf(al2, v1_.z, nm2) : -200.0f);    \
        float e7 = ex2f((fg_ & 128u) ? fmaf(al2, v1_.w, nm2) : -200.0f);    \
        __half2 p0 = __floats2half2_rn(e0, e1);                             \
        __half2 p1 = __floats2half2_rn(e2, e3);                             \
        __half2 p2 = __floats2half2_rn(e4, e5);                             \
        __half2 p3 = __floats2half2_rn(e6, e7);                             \
        uint4 vv_ = make_uint4(*(unsigned*)&p0, *(unsigned*)&p1,            \
                               *(unsigned*)&p2, *(unsigned*)&p3);           \
        *(uint4*)(dst_ + 4 * g_) = vv_;                                     \
    }                                                                       \
} while (0)

#define LOAD_B(IT, BUF) do {                                                \
    int ku_ = (IT) * 32;                                                    \
    unsigned char* db_ = sm + ((BUF) ? SM_B1 : SM_B0);                      \
    cp16(db_ + br0 * 144 + bc * 16, &XTu[(size_t)br0 * (NN / 2) + ku_ + bc * 4]); \
    cp16(db_ + br1 * 144 + bc * 16, &XTu[(size_t)br1 * (NN / 2) + ku_ + bc * 4]); \
    if (tid < 64)                                                           \
        cp16(db_ + br2 * 144 + bc * 16, &XTu[(size_t)br2 * (NN / 2) + ku_ + bc * 4]); \
    asm volatile("cp.async.commit_group;\n" ::: "memory");                  \
} while (0)

    BUILD_A(0, 0);
    LOAD_B(0, 0);

    for (int it = 0; it < 64; it++) {
        int buf = it & 1;
        if (it < 63) {
            BUILD_A(it + 1, buf ^ 1);
            LOAD_B(it + 1, buf ^ 1);
            asm volatile("cp.async.wait_group 1;\n" ::: "memory");
        } else {
            asm volatile("cp.async.wait_group 0;\n" ::: "memory");
        }
        __syncthreads();

        uint32_t abuf = buf ? (SM_A1 - SM_A0) : 0;
        uint32_t bbuf = buf ? (SM_B1 - SM_B0) : 0;
#pragma unroll
        for (int ki = 0; ki < 4; ki++) {
            uint32_t a0, a1, a2, a3, b0, b1, b2, b3;
            ldsm4(a0, a1, a2, a3, aA + abuf + ki * 32);
            ldsm4(b0, b1, b2, b3, bA0 + bbuf + ki * 32);
            HMMA(acc[0], a0, a1, a2, a3, b0, b1);
            HMMA(acc[1], a0, a1, a2, a3, b2, b3);
            ldsm4(b0, b1, b2, b3, bA1 + bbuf + ki * 32);
            HMMA(acc[2], a0, a1, a2, a3, b0, b1);
            HMMA(acc[3], a0, a1, a2, a3, b2, b3);
            if (nw == 0) {
                ldsm2(b0, b1, bA2 + bbuf + ki * 32);
                HMMA(acc[4], a0, a1, a2, a3, b0, b1);
            }
        }
        __syncthreads();
    }

    // ---- epilogue: dump, normalize by ones-column, relu, store ----
    int ncnt = nw ? 4 : 5;
#pragma unroll
    for (int ni = 0; ni < 5; ni++) {
        if (ni < ncnt) {
            int r0 = mw * 16 + gid;
            int cc = (nw ? 40 : 0) + ni * 8 + tig * 2;
            Cs[(r0)     * 73 + cc]     = acc[ni][0];
            Cs[(r0)     * 73 + cc + 1] = acc[ni][1];
            Cs[(r0 + 8) * 73 + cc]     = acc[ni][2];
            Cs[(r0 + 8) * 73 + cc + 1] = acc[ni][3];
        }
    }
    __syncthreads();
#pragma unroll
    for (int q = 0; q < 16; q++) {
        int idx = q * 256 + tid;
        int rr = idx >> 6, c = idx & 63;
        float z = Cs[rr * 73 + 64];
        float v = Cs[rr * 73 + c];
        v = (z > 0.0f) ? (v / z) : 0.0f;
        out[(size_t)(i0 + rr) * HC + h * NC + c] = fmaxf(v, 0.0f);
    }
}

// =================================================================
extern "C" void kernel_launch(void* const* d_in, const int* in_sizes, int n_in,
                              void* d_out, int out_size) {
    const float* x     = (const float*)d_in[0];
    const int*   adj   = (const int*)d_in[1];
    const float* W     = (const float*)d_in[2];
    const float* b     = (const float*)d_in[3];
    const float* att_l = (const float*)d_in[4];
    const float* att_r = (const float*)d_in[5];
    float* out = (float*)d_out;

    k_prep<<<4641, 256>>>(adj, W, b, att_l, att_r);
    k_alpha<<<NN, 256>>>(x);
    k_xl16<<<NN / 128 * NH, 256>>>(x, W);
    k_aggF3<<<dim3(NN / 64, NH), 256>>>(out);
}

// round 17
// speedup vs baseline: 3.2618x; 1.2766x over previous
#include <cuda_runtime.h>
#include <cuda_fp16.h>
#include <cuda_bf16.h>
#include <math.h>
#include <stdint.h>

#define NN 4096
#define NF 512
#define NH 8
#define NC 64
#define HC 512
#define TC 72

// -------- scratch --------
__device__ float    g_wl[NH * NF], g_wr[NH * NF];
__device__ float    g_bl[NH], g_br[NH];
__device__ float    g_blb[HC];
__device__ float    g_alT[NH * NN];                 // alpha_l [h][n]
__device__ float    g_arT[NH * NN];                 // alpha_r [h][n]
__device__ unsigned g_rmaxu[NH], g_rminu[NH];
__device__ __half   g_XT[(size_t)NH * TC * NN];     // X-tilde transposed [h][c][j]
__device__ unsigned g_adjbits[(size_t)NN * 128];    // adj bitmask, 2MB

__device__ __forceinline__ unsigned fmono(float f) {
    unsigned u = __float_as_uint(f);
    return (u & 0x80000000u) ? ~u : (u | 0x80000000u);
}
__device__ __forceinline__ float fdec(unsigned u) {
    return __uint_as_float((u & 0x80000000u) ? (u ^ 0x80000000u) : ~u);
}
__device__ __forceinline__ uint32_t s2u(const void* p) {
    uint32_t a;
    asm("{ .reg .u64 t; cvta.to.shared.u64 t, %1; cvt.u32.u64 %0, t; }" : "=r"(a) : "l"(p));
    return a;
}
__device__ __forceinline__ float ex2f(float x) {
    float y; asm("ex2.approx.ftz.f32 %0, %1;" : "=f"(y) : "f"(x)); return y;
}
__device__ __forceinline__ void cp16(void* dst, const void* src) {
    unsigned d = (unsigned)__cvta_generic_to_shared(dst);
    asm volatile("cp.async.cg.shared.global [%0], [%1], 16;\n" :: "r"(d), "l"(src));
}
__device__ __forceinline__ void ldsm4(uint32_t& r0, uint32_t& r1, uint32_t& r2,
                                      uint32_t& r3, uint32_t a) {
    asm volatile("ldmatrix.sync.aligned.m8n8.x4.shared.b16 {%0,%1,%2,%3}, [%4];"
                 : "=r"(r0), "=r"(r1), "=r"(r2), "=r"(r3) : "r"(a));
}
__device__ __forceinline__ void ldsm2(uint32_t& r0, uint32_t& r1, uint32_t a) {
    asm volatile("ldmatrix.sync.aligned.m8n8.x2.shared.b16 {%0,%1}, [%2];"
                 : "=r"(r0), "=r"(r1) : "r"(a));
}
#define HMMA(ACC, A0, A1, A2, A3, B0, B1)                                   \
    asm volatile(                                                           \
        "mma.sync.aligned.m16n8k16.row.col.f32.f16.f16.f32 "                \
        "{%0,%1,%2,%3}, {%4,%5,%6,%7}, {%8,%9}, {%0,%1,%2,%3};\n"           \
        : "+f"((ACC)[0]), "+f"((ACC)[1]), "+f"((ACC)[2]), "+f"((ACC)[3])    \
        : "r"(A0), "r"(A1), "r"(A2), "r"(A3), "r"(B0), "r"(B1))

// =================================================================
// K1: pack adj | prepw | XT tail rows | stat init | bias copy
// =================================================================
__global__ void __launch_bounds__(256) k_prep(const int* __restrict__ adj,
                                              const float* __restrict__ W,
                                              const float* __restrict__ b,
                                              const float* __restrict__ attl,
                                              const float* __restrict__ attr) {
    int bb = blockIdx.x, tid = threadIdx.x;
    if (bb < 4096) {
        int warp = tid >> 5, lane = tid & 31;
        const int* row = adj + (size_t)bb * NN;
#pragma unroll
        for (int w = warp; w < 128; w += 8) {
            int v = __ldg(&row[w * 32 + lane]);
            unsigned m = __ballot_sync(0xFFFFFFFFu, v > 0);
            if (lane == 0) g_adjbits[bb * 128 + w] = m;
        }
    } else if (bb < 4128) {
        int idx = (bb - 4096) * 256 + tid;
        int side = idx >> 12;
        int h = (idx >> 9) & 7;
        int k = idx & 511;
        const float* av = (side ? attr : attl) + h * NC;
        const float* wr = W + (size_t)k * HC + h * NC;
        float s = 0.0f;
#pragma unroll
        for (int c = 0; c < NC; c++) s = fmaf(wr[c], av[c], s);
        (side ? g_wr : g_wl)[h * NF + k] = s;
        if (idx < 16) {
            int sd = idx >> 3, hh = idx & 7;
            const float* av2 = (sd ? attr : attl) + hh * NC;
            float s2 = 0.0f;
#pragma unroll
            for (int c = 0; c < NC; c++) s2 = fmaf(b[hh * NC + c], av2[c], s2);
            (sd ? g_br : g_bl)[hh] = s2;
        }
        if (bb == 4096) {
            g_blb[tid] = b[tid];
            g_blb[tid + 256] = b[tid + 256];
        }
    } else if (bb < 4640) {
        int idx = (bb - 4128) * 256 + tid;
        int h = idx >> 14;
        int rem = idx & 16383;
        int c = 64 + (rem >> 11);
        int ju = rem & 2047;
        ((unsigned*)g_XT)[((size_t)h * TC + c) * (NN / 2) + ju] =
            (c == 64) ? 0x3C003C00u : 0u;
    } else {
        if (tid < NH) { g_rmaxu[tid] = 0u; g_rminu[tid] = 0xFFFFFFFFu; }
    }
}

// =================================================================
// K2: exact fp32 alphas + atomic per-head max/min of alpha_r
// =================================================================
__global__ void __launch_bounds__(256) k_alpha(const float* __restrict__ x) {
    __shared__ float sx[NF];
    int n = blockIdx.x;
    int tid = threadIdx.x;
    sx[tid]       = x[(size_t)n * NF + tid];
    sx[tid + 256] = x[(size_t)n * NF + tid + 256];
    __syncthreads();
    int w = tid >> 5, lane = tid & 31;
    float sl = 0.0f, sr = 0.0f;
#pragma unroll
    for (int i = 0; i < 16; i++) {
        float xv = sx[lane + 32 * i];
        sl = fmaf(xv, g_wl[w * NF + lane + 32 * i], sl);
        sr = fmaf(xv, g_wr[w * NF + lane + 32 * i], sr);
    }
#pragma unroll
    for (int o = 16; o; o >>= 1) {
        sl += __shfl_xor_sync(0xFFFFFFFFu, sl, o);
        sr += __shfl_xor_sync(0xFFFFFFFFu, sr, o);
    }
    if (lane == 0) {
        float vr = sr + g_br[w];
        g_alT[w * NN + n] = sl + g_bl[w];
        g_arT[w * NN + n] = vr;
        unsigned um = fmono(vr);
        atomicMax(&g_rmaxu[w], um);
        atomicMin(&g_rminu[w], um);
    }
}

// =================================================================
// K3: xl16: x@W+b (fp16 MMA) -> XT[h][c][j] transposed
// =================================================================
__global__ void __launch_bounds__(256) k_xl16(const float* __restrict__ x,
                                              const float* __restrict__ W) {
    __shared__ __align__(16) unsigned sAu[128 * 18];
    __shared__ __align__(16) unsigned sBu[64 * 18];
    __half* sBh = (__half*)sBu;
    int bb = blockIdx.x;
    int h = bb & 7;
    int m0 = (bb >> 3) * 128;
    int tid = threadIdx.x;
    int warp = tid >> 5, lane = tid & 31;
    int gid = lane >> 2, tig = lane & 3;
    int mw = warp & 3, nw = warp >> 2;

    float acc[2][4][4];
#pragma unroll
    for (int mi = 0; mi < 2; mi++)
#pragma unroll
        for (int ni = 0; ni < 4; ni++)
#pragma unroll
            for (int q = 0; q < 4; q++) acc[mi][ni][q] = 0.0f;

    for (int k0 = 0; k0 < NF; k0 += 32) {
#pragma unroll
        for (int q = 0; q < 8; q++) {
            int u = q * 256 + tid;
            int r = u >> 4, cp = u & 15;
            float2 v = *(const float2*)(x + (size_t)(m0 + r) * NF + k0 + 2 * cp);
            __half2 hh = __floats2half2_rn(v.x, v.y);
            sAu[r * 18 + cp] = *(unsigned*)&hh;
        }
#pragma unroll
        for (int q = 0; q < 8; q++) {
            int idx = q * 256 + tid;
            int r = idx >> 6, c = idx & 63;
            float v = W[(size_t)(k0 + r) * HC + h * NC + c];
            sBh[c * 36 + r] = __float2half(v);
        }
        __syncthreads();
#pragma unroll
        for (int ki = 0; ki < 2; ki++) {
            unsigned af[2][4];
#pragma unroll
            for (int mi = 0; mi < 2; mi++) {
                int r0 = mw * 32 + mi * 16 + gid;
                af[mi][0] = sAu[(r0)     * 18 + ki * 8 + tig];
                af[mi][1] = sAu[(r0 + 8) * 18 + ki * 8 + tig];
                af[mi][2] = sAu[(r0)     * 18 + ki * 8 + tig + 4];
                af[mi][3] = sAu[(r0 + 8) * 18 + ki * 8 + tig + 4];
            }
#pragma unroll
            for (int ni = 0; ni < 4; ni++) {
                int n = nw * 32 + ni * 8 + gid;
                unsigned b0 = sBu[n * 18 + ki * 8 + tig];
                unsigned b1 = sBu[n * 18 + ki * 8 + tig + 4];
#pragma unroll
                for (int mi = 0; mi < 2; mi++) {
                    asm volatile(
                        "mma.sync.aligned.m16n8k16.row.col.f32.f16.f16.f32 "
                        "{%0,%1,%2,%3}, {%4,%5,%6,%7}, {%8,%9}, {%0,%1,%2,%3};\n"
                        : "+f"(acc[mi][ni][0]), "+f"(acc[mi][ni][1]),
                          "+f"(acc[mi][ni][2]), "+f"(acc[mi][ni][3])
                        : "r"(af[mi][0]), "r"(af[mi][1]),
                          "r"(af[mi][2]), "r"(af[mi][3]),
                          "r"(b0), "r"(b1));
                }
            }
        }
        __syncthreads();
    }
    __half* XTh = g_XT + (size_t)h * TC * NN;
#pragma unroll
    for (int mi = 0; mi < 2; mi++)
#pragma unroll
        for (int ni = 0; ni < 4; ni++) {
            int r0 = m0 + mw * 32 + mi * 16 + gid;
            int cc = nw * 32 + ni * 8 + tig * 2;
            float b0 = g_blb[h * NC + cc];
            float b1 = g_blb[h * NC + cc + 1];
            XTh[(size_t)(cc)     * NN + r0]     = __float2half(acc[mi][ni][0] + b0);
            XTh[(size_t)(cc + 1) * NN + r0]     = __float2half(acc[mi][ni][1] + b1);
            XTh[(size_t)(cc)     * NN + r0 + 8] = __float2half(acc[mi][ni][2] + b0);
            XTh[(size_t)(cc + 1) * NN + r0 + 8] = __float2half(acc[mi][ni][3] + b1);
        }
}

// =================================================================
// K4: fused aggregation v4 — MT=128, m32 per warp (4m x 2n), dynamic
// smem 57600B: A x2 (128 x 144B) | B x2 (72 x 144B). KT=64.
// grid (32, 8), 256 thr. Each warp: acc[2][5][4].
// =================================================================
#define SM_A0 0
#define SM_A1 18432
#define SM_B0 36864
#define SM_B1 47232
#define SM_TOT 57600
__global__ void __launch_bounds__(256, 2) k_aggF4(float* __restrict__ out) {
    extern __shared__ __align__(16) unsigned char sm[];
    uint32_t smb = s2u(sm);
    float* Cs = (float*)sm;                     // epilogue overlay [128][73]

    int h = blockIdx.y;
    int i0 = blockIdx.x * 128;
    int tid = threadIdx.x;
    int warp = tid >> 5, lane = tid & 31;
    int gid = lane >> 2, tig = lane & 3;
    int mw = warp & 3, nw = warp >> 2;

    // ---- builder roles: 2 units per thread; unit u -> row u>>2, quad u&3 ----
    int r0u = tid >> 2, r1u = (tid + 256) >> 2;     // rows (r1u = r0u + 64)
    int qq = tid & 3;
    float al2[2], nm2[2];
    {
        float rmx = fdec(g_rmaxu[h]), rmn = fdec(g_rminu[h]);
        const float L2E = 1.4426950408889634f;
#pragma unroll
        for (int u2 = 0; u2 < 2; u2++) {
            int rr = u2 ? r1u : r0u;
            float al = g_alT[h * NN + i0 + rr];
            float mm = (al >= 0.0f) ? al * rmx : al * rmn;
            al2[u2] = al * L2E; nm2[u2] = -mm * L2E;
        }
    }
    const unsigned* bits0 = g_adjbits + (size_t)(i0 + r0u) * 128 + (qq >> 1);
    const unsigned* bits1 = g_adjbits + (size_t)(i0 + r1u) * 128 + (qq >> 1);
    int shb = (qq & 1) * 16;
    const float* arbase = g_arT + h * NN + qq * 16;  // L1-resident (16KB/head)

    // ---- B cp.async roles (72 rows x 128B) ----
    const unsigned* XTu = (const unsigned*)(g_XT + (size_t)h * TC * NN);
    int br0 = tid >> 3,         bc = tid & 7;
    int br1 = (tid + 256) >> 3;
    int br2 = (tid + 512) >> 3;

    // ---- ldmatrix lane addresses ----
    uint32_t aA = smb + SM_A0 + (mw * 32 + (lane & 15)) * 144 + ((lane >> 4) & 1) * 16;
    int nbase = nw ? 40 : 0;
    uint32_t bA0 = smb + SM_B0 +
                   (nbase + (lane & 7) + ((lane >> 4) & 1) * 8) * 144 +
                   ((lane >> 3) & 1) * 16;
    uint32_t bA1 = bA0 + 16 * 144;
    uint32_t bA2 = smb + SM_B0 + (32 + (lane & 7)) * 144 + ((lane >> 3) & 1) * 16;

    float acc[2][5][4];
#pragma unroll
    for (int mi = 0; mi < 2; mi++)
#pragma unroll
        for (int ni = 0; ni < 5; ni++)
#pragma unroll
            for (int q = 0; q < 4; q++) acc[mi][ni][q] = 0.0f;

#define BUILD_HALF(IT, BUF, U2, RR, BITS) do {                              \
    unsigned f_ = (__ldg(&(BITS)[(IT) * 2]) >> shb) & 0xFFFFu;              \
    const float4* ap_ = (const float4*)(arbase + (IT) * 64);                \
    unsigned* dst_ = (unsigned*)(sm + ((BUF) ? SM_A1 : SM_A0)) + (RR) * 36 + qq * 8; \
    float A2_ = al2[U2], N2_ = nm2[U2];                                     \
    _Pragma("unroll")                                                       \
    for (int g_ = 0; g_ < 2; g_++) {                                        \
        float4 v0_ = __ldg(&ap_[2 * g_]);                                   \
        float4 v1_ = __ldg(&ap_[2 * g_ + 1]);                               \
        unsigned fg_ = f_ >> (8 * g_);                                      \
        float e0 = ex2f((fg_ & 1u)   ? fmaf(A2_, v0_.x, N2_) : -200.0f);    \
        float e1 = ex2f((fg_ & 2u)   ? fmaf(A2_, v0_.y, N2_) : -200.0f);    \
        float e2 = ex2f((fg_ & 4u)   ? fmaf(A2_, v0_.z, N2_) : -200.0f);    \
        float e3 = ex2f((fg_ & 8u)   ? fmaf(A2_, v0_.w, N2_) : -200.0f);    \
        float e4 = ex2f((fg_ & 16u)  ? fmaf(A2_, v1_.x, N2_) : -200.0f);    \
        float e5 = ex2f((fg_ & 32u)  ? fmaf(A2_, v1_.y, N2_) : -200.0f);    \
        float e6 = ex2f((fg_ & 64u)  ? fmaf(A2_, v1_.z, N2_) : -200.0f);    \
        float e7 = ex2f((fg_ & 128u) ? fmaf(A2_, v1_.w, N2_) : -200.0f);    \
        __half2 p0 = __floats2half2_rn(e0, e1);                             \
        __half2 p1 = __floats2half2_rn(e2, e3);                             \
        __half2 p2 = __floats2half2_rn(e4, e5);                             \
        __half2 p3 = __floats2half2_rn(e6, e7);                             \
        uint4 vv_ = make_uint4(*(unsigned*)&p0, *(unsigned*)&p1,            \
                               *(unsigned*)&p2, *(unsigned*)&p3);           \
        *(uint4*)(dst_ + 4 * g_) = vv_;                                     \
    }                                                                       \
} while (0)

#define BUILD_A(IT, BUF) do {                                               \
    BUILD_HALF(IT, BUF, 0, r0u, bits0);                                     \
    BUILD_HALF(IT, BUF, 1, r1u, bits1);                                     \
} while (0)

#define LOAD_B(IT, BUF) do {                                                \
    int ku_ = (IT) * 32;                                                    \
    unsigned char* db_ = sm + ((BUF) ? SM_B1 : SM_B0);                      \
    cp16(db_ + br0 * 144 + bc * 16, &XTu[(size_t)br0 * (NN / 2) + ku_ + bc * 4]); \
    cp16(db_ + br1 * 144 + bc * 16, &XTu[(size_t)br1 * (NN / 2) + ku_ + bc * 4]); \
    if (tid < 64)                                                           \
        cp16(db_ + br2 * 144 + bc * 16, &XTu[(size_t)br2 * (NN / 2) + ku_ + bc * 4]); \
    asm volatile("cp.async.commit_group;\n" ::: "memory");                  \
} while (0)

    BUILD_A(0, 0);
    LOAD_B(0, 0);

    for (int it = 0; it < 64; it++) {
        int buf = it & 1;
        if (it < 63) {
            BUILD_A(it + 1, buf ^ 1);
            LOAD_B(it + 1, buf ^ 1);
            asm volatile("cp.async.wait_group 1;\n" ::: "memory");
        } else {
            asm volatile("cp.async.wait_group 0;\n" ::: "memory");
        }
        __syncthreads();

        uint32_t abuf = buf ? (SM_A1 - SM_A0) : 0;
        uint32_t bbuf = buf ? (SM_B1 - SM_B0) : 0;
#pragma unroll
        for (int ki = 0; ki < 4; ki++) {
            uint32_t a0[2], a1[2], a2[2], a3[2];
#pragma unroll
            for (int mi = 0; mi < 2; mi++)
                ldsm4(a0[mi], a1[mi], a2[mi], a3[mi],
                      aA + abuf + mi * (16 * 144) + ki * 32);
            uint32_t b0, b1, b2, b3;
            ldsm4(b0, b1, b2, b3, bA0 + bbuf + ki * 32);
#pragma unroll
            for (int mi = 0; mi < 2; mi++) {
                HMMA(acc[mi][0], a0[mi], a1[mi], a2[mi], a3[mi], b0, b1);
                HMMA(acc[mi][1], a0[mi], a1[mi], a2[mi], a3[mi], b2, b3);
            }
            ldsm4(b0, b1, b2, b3, bA1 + bbuf + ki * 32);
#pragma unroll
            for (int mi = 0; mi < 2; mi++) {
                HMMA(acc[mi][2], a0[mi], a1[mi], a2[mi], a3[mi], b0, b1);
                HMMA(acc[mi][3], a0[mi], a1[mi], a2[mi], a3[mi], b2, b3);
            }
            if (nw == 0) {
                ldsm2(b0, b1, bA2 + bbuf + ki * 32);
#pragma unroll
                for (int mi = 0; mi < 2; mi++)
                    HMMA(acc[mi][4], a0[mi], a1[mi], a2[mi], a3[mi], b0, b1);
            }
        }
        __syncthreads();
    }

    // ---- epilogue: dump, normalize by ones-column, relu, store ----
    int ncnt = nw ? 4 : 5;
#pragma unroll
    for (int mi = 0; mi < 2; mi++)
#pragma unroll
        for (int ni = 0; ni < 5; ni++) {
            if (ni < ncnt) {
                int rr = mw * 32 + mi * 16 + gid;
                int cc = (nw ? 40 : 0) + ni * 8 + tig * 2;
                Cs[(rr)     * 73 + cc]     = acc[mi][ni][0];
                Cs[(rr)     * 73 + cc + 1] = acc[mi][ni][1];
                Cs[(rr + 8) * 73 + cc]     = acc[mi][ni][2];
                Cs[(rr + 8) * 73 + cc + 1] = acc[mi][ni][3];
            }
        }
    __syncthreads();
#pragma unroll
    for (int q = 0; q < 32; q++) {
        int idx = q * 256 + tid;
        int rr = idx >> 6, c = idx & 63;
        float z = Cs[rr * 73 + 64];
        float v = Cs[rr * 73 + c];
        v = (z > 0.0f) ? (v / z) : 0.0f;
        out[(size_t)(i0 + rr) * HC + h * NC + c] = fmaxf(v, 0.0f);
    }
}

// =================================================================
extern "C" void kernel_launch(void* const* d_in, const int* in_sizes, int n_in,
                              void* d_out, int out_size) {
    const float* x     = (const float*)d_in[0];
    const int*   adj   = (const int*)d_in[1];
    const float* W     = (const float*)d_in[2];
    const float* b     = (const float*)d_in[3];
    const float* att_l = (const float*)d_in[4];
    const float* att_r = (const float*)d_in[5];
    float* out = (float*)d_out;

    cudaFuncSetAttribute(k_aggF4, cudaFuncAttributeMaxDynamicSharedMemorySize, SM_TOT);
    k_prep<<<4641, 256>>>(adj, W, b, att_l, att_r);
    k_alpha<<<NN, 256>>>(x);
    k_xl16<<<NN / 128 * NH, 256>>>(x, W);
    k_aggF4<<<dim3(NN / 128, NH), 256, SM_TOT>>>(out);
}